// round 1
// baseline (speedup 1.0000x reference)
#include <cuda_runtime.h>
#include <math.h>

#define NN 50000
#define NE 800000
#define DHID 128      // HEADS * D_HEAD
#define NH 4
#define DHEAD 32
#define OUTD 512
#define NEG_SLOPE 0.2f
#define EPSV 1e-9f

// ---------------- scratch (device globals; no allocation) ----------------
__device__ float g_Wh[NN * DHID];     // Wh of current layer
__device__ float g_z[NN * DHID];      // layer-1 output (post ELU)
__device__ float g_out[NN * DHID];    // aggregation accumulator
__device__ float g_el[NN * NH];
__device__ float g_er[NN * NH];
__device__ float g_m[NN * NH];
__device__ float g_den[NN * NH];
__device__ float g_rden[NN * NH];
__device__ float g_ex[NE * NH];
__device__ float g_z2[NN * DHEAD];    // layer-2 mean output

// ---------------- helpers ----------------
__device__ __forceinline__ void atomicMaxF(float* addr, float v) {
    if (v >= 0.0f) atomicMax((int*)addr, __float_as_int(v));
    else           atomicMin((unsigned int*)addr, __float_as_uint(v));
}

__device__ __forceinline__ float lrelu(float x) {
    return x > 0.0f ? x : NEG_SLOPE * x;
}

// ---------------- generic register-tiled SGEMM (+optional bias) ----------------
// C[M,N] = A[M,K] @ B[K,N] (+ bias[N]);  N multiple of 64, K multiple of 32.
template <int BM, int BN, int BK, int TM, int TN>
__global__ void sgemm_bias(const float* __restrict__ A, const float* __restrict__ B,
                           const float* __restrict__ bias, float* __restrict__ C,
                           int M, int N, int K) {
    __shared__ float As[BK][BM + 1];
    __shared__ float Bs[BK][BN + 1];
    const int tid = threadIdx.x;                 // 256 threads
    const int tx = tid % (BN / TN);              // 16
    const int ty = tid / (BN / TN);              // 16
    const int rowBase = blockIdx.y * BM;
    const int colBase = blockIdx.x * BN;

    float acc[TM][TN];
#pragma unroll
    for (int i = 0; i < TM; i++)
#pragma unroll
        for (int j = 0; j < TN; j++) acc[i][j] = 0.0f;

    for (int k0 = 0; k0 < K; k0 += BK) {
        for (int i = tid; i < BM * BK; i += 256) {
            int r = i / BK, kk = i % BK;
            int gr = rowBase + r;
            As[kk][r] = (gr < M) ? A[gr * K + k0 + kk] : 0.0f;
        }
        for (int i = tid; i < BK * BN; i += 256) {
            int kk = i / BN, c = i % BN;
            Bs[kk][c] = B[(k0 + kk) * N + colBase + c];
        }
        __syncthreads();
#pragma unroll
        for (int kk = 0; kk < BK; kk++) {
            float a[TM], b[TN];
#pragma unroll
            for (int i = 0; i < TM; i++) a[i] = As[kk][ty * TM + i];
#pragma unroll
            for (int j = 0; j < TN; j++) b[j] = Bs[kk][tx * TN + j];
#pragma unroll
            for (int i = 0; i < TM; i++)
#pragma unroll
                for (int j = 0; j < TN; j++) acc[i][j] = fmaf(a[i], b[j], acc[i][j]);
        }
        __syncthreads();
    }

#pragma unroll
    for (int i = 0; i < TM; i++) {
        int row = rowBase + ty * TM + i;
        if (row >= M) continue;
#pragma unroll
        for (int j = 0; j < TN; j++) {
            int col = colBase + tx * TN + j;
            float v = acc[i][j];
            if (bias) v += bias[col];
            C[row * N + col] = v;
        }
    }
}

// ---------------- attention coefficients: el/er per (node, head) ----------------
// one block per node, 128 threads; warp w == head w
__global__ void k_attn_coef(const float* __restrict__ al, const float* __restrict__ ar) {
    int n = blockIdx.x;
    int d = threadIdx.x;                  // 0..127
    float w = g_Wh[n * DHID + d];
    float pl = w * al[d];
    float pr = w * ar[d];
#pragma unroll
    for (int o = 16; o > 0; o >>= 1) {
        pl += __shfl_down_sync(0xFFFFFFFFu, pl, o);
        pr += __shfl_down_sync(0xFFFFFFFFu, pr, o);
    }
    if ((d & 31) == 0) {
        int h = d >> 5;
        g_el[n * NH + h] = pl;
        g_er[n * NH + h] = pr;
    }
}

// ---------------- per-layer init: out=0, m=-inf, den=0 ----------------
__global__ void k_init() {
    int i = blockIdx.x * blockDim.x + threadIdx.x;
    if (i < NN * DHID) g_out[i] = 0.0f;
    if (i < NN * NH) { g_m[i] = -INFINITY; g_den[i] = 0.0f; }
}

// ---------------- edge pass 1: leakyrelu(e) -> segment max ----------------
__global__ void k_edge_max(const int* __restrict__ src, const int* __restrict__ dst) {
    int e = blockIdx.x * blockDim.x + threadIdx.x;
    if (e >= NE) return;
    int s = src[e], t = dst[e];
    float4 el = *(const float4*)(g_el + s * NH);
    float4 er = *(const float4*)(g_er + t * NH);
    float v0 = lrelu(el.x + er.x);
    float v1 = lrelu(el.y + er.y);
    float v2 = lrelu(el.z + er.z);
    float v3 = lrelu(el.w + er.w);
    atomicMaxF(&g_m[t * NH + 0], v0);
    atomicMaxF(&g_m[t * NH + 1], v1);
    atomicMaxF(&g_m[t * NH + 2], v2);
    atomicMaxF(&g_m[t * NH + 3], v3);
}

__global__ void k_fix_m() {
    int i = blockIdx.x * blockDim.x + threadIdx.x;
    if (i >= NN * NH) return;
    float v = g_m[i];
    g_m[i] = isfinite(v) ? v : 0.0f;
}

// ---------------- edge pass 2: ex = exp(e - m[dst]) ; den[dst] += ex ----------------
__global__ void k_edge_exp(const int* __restrict__ src, const int* __restrict__ dst) {
    int e = blockIdx.x * blockDim.x + threadIdx.x;
    if (e >= NE) return;
    int s = src[e], t = dst[e];
    float4 el = *(const float4*)(g_el + s * NH);
    float4 er = *(const float4*)(g_er + t * NH);
    float4 m4 = *(const float4*)(g_m + t * NH);
    float4 ex;
    ex.x = __expf(lrelu(el.x + er.x) - m4.x);
    ex.y = __expf(lrelu(el.y + er.y) - m4.y);
    ex.z = __expf(lrelu(el.z + er.z) - m4.z);
    ex.w = __expf(lrelu(el.w + er.w) - m4.w);
    *(float4*)(g_ex + e * NH) = ex;
    atomicAdd(&g_den[t * NH + 0], ex.x);
    atomicAdd(&g_den[t * NH + 1], ex.y);
    atomicAdd(&g_den[t * NH + 2], ex.z);
    atomicAdd(&g_den[t * NH + 3], ex.w);
}

__global__ void k_rden() {
    int i = blockIdx.x * blockDim.x + threadIdx.x;
    if (i >= NN * NH) return;
    g_rden[i] = 1.0f / (g_den[i] + EPSV);
}

// ---------------- edge pass 3: out[dst] += alpha * Wh[src] ----------------
// 256 threads per block = 2 edges x 128 dims
__global__ void k_scatter(const int* __restrict__ src, const int* __restrict__ dst) {
    int e = blockIdx.x * 2 + (threadIdx.x >> 7);
    if (e >= NE) return;
    int d = threadIdx.x & (DHID - 1);
    int s = src[e], t = dst[e];
    int h = d >> 5;
    float alpha = g_ex[e * NH + h] * g_rden[t * NH + h];
    atomicAdd(&g_out[t * DHID + d], alpha * g_Wh[s * DHID + d]);
}

// ---------------- finalize layer 1: z = elu(out + b1) ----------------
__global__ void k_final1(const float* __restrict__ b1) {
    int i = blockIdx.x * blockDim.x + threadIdx.x;
    if (i >= NN * DHID) return;
    float v = g_out[i] + b1[i & (DHID - 1)];
    g_z[i] = v > 0.0f ? v : (__expf(v) - 1.0f);
}

// ---------------- finalize layer 2: z2 = mean over heads of (out + b2) ----------------
__global__ void k_final2(const float* __restrict__ b2) {
    int i = blockIdx.x * blockDim.x + threadIdx.x;
    if (i >= NN * DHEAD) return;
    int n = i / DHEAD, j = i % DHEAD;
    float sum = 0.0f;
#pragma unroll
    for (int h = 0; h < NH; h++)
        sum += g_out[n * DHID + h * DHEAD + j] + b2[h * DHEAD + j];
    g_z2[i] = 0.25f * sum;
}

// ---------------- launch ----------------
extern "C" void kernel_launch(void* const* d_in, const int* in_sizes, int n_in,
                              void* d_out, int out_size) {
    const float* h   = (const float*)d_in[0];
    const int*   src = (const int*)d_in[1];
    const int*   dst = (const int*)d_in[2];
    const float* W1  = (const float*)d_in[3];
    const float* al1 = (const float*)d_in[4];
    const float* ar1 = (const float*)d_in[5];
    const float* b1  = (const float*)d_in[6];
    const float* W2  = (const float*)d_in[7];
    const float* al2 = (const float*)d_in[8];
    const float* ar2 = (const float*)d_in[9];
    const float* b2  = (const float*)d_in[10];
    const float* Wp  = (const float*)d_in[11];
    const float* bp  = (const float*)d_in[12];
    float* out = (float*)d_out;

    float *p_Wh, *p_z, *p_z2;
    cudaGetSymbolAddress((void**)&p_Wh, g_Wh);
    cudaGetSymbolAddress((void**)&p_z,  g_z);
    cudaGetSymbolAddress((void**)&p_z2, g_z2);

    const int TPB = 256;
    dim3 gemmBlk(256);
    dim3 gemmGrid1(DHID / 64, (NN + 63) / 64);     // N=128
    dim3 gemmGridP(OUTD / 64, (NN + 63) / 64);     // N=512

    int gInit   = (NN * DHID + TPB - 1) / TPB;
    int gEdge   = (NE + TPB - 1) / TPB;
    int gSmall  = (NN * NH + TPB - 1) / TPB;
    int gScat   = (NE + 1) / 2;
    int gFin2   = (NN * DHEAD + TPB - 1) / TPB;

    // ===== layer 1 =====
    sgemm_bias<64, 64, 32, 4, 4><<<gemmGrid1, gemmBlk>>>(h, W1, nullptr, p_Wh, NN, DHID, DHID);
    k_attn_coef<<<NN, 128>>>(al1, ar1);
    k_init<<<gInit, TPB>>>();
    k_edge_max<<<gEdge, TPB>>>(src, dst);
    k_fix_m<<<gSmall, TPB>>>();
    k_edge_exp<<<gEdge, TPB>>>(src, dst);
    k_rden<<<gSmall, TPB>>>();
    k_scatter<<<gScat, TPB>>>(src, dst);
    k_final1<<<gInit, TPB>>>(b1);

    // ===== layer 2 =====
    sgemm_bias<64, 64, 32, 4, 4><<<gemmGrid1, gemmBlk>>>(p_z, W2, nullptr, p_Wh, NN, DHID, DHID);
    k_attn_coef<<<NN, 128>>>(al2, ar2);
    k_init<<<gInit, TPB>>>();
    k_edge_max<<<gEdge, TPB>>>(src, dst);
    k_fix_m<<<gSmall, TPB>>>();
    k_edge_exp<<<gEdge, TPB>>>(src, dst);
    k_rden<<<gSmall, TPB>>>();
    k_scatter<<<gScat, TPB>>>(src, dst);
    k_final2<<<gFin2, TPB>>>(b2);

    // ===== projection head =====
    sgemm_bias<64, 64, 32, 4, 4><<<gemmGridP, gemmBlk>>>(p_z2, Wp, bp, out, NN, OUTD, DHEAD);
}

// round 2
// speedup vs baseline: 1.8304x; 1.8304x over previous
#include <cuda_runtime.h>
#include <math.h>

#define NN 50000
#define NE 800000
#define DHID 128
#define NH 4
#define DHEAD 32
#define OUTD 512
#define NEG_SLOPE 0.2f
#define EPSV 1e-9f

// ---------------- scratch (device globals; no allocation) ----------------
__device__ float g_Wh[NN * DHID];
__device__ float g_z[NN * DHID];
__device__ float g_el[NN * NH];
__device__ float g_er[NN * NH];
__device__ float g_z2[NN * DHEAD];
__device__ int   g_cnt[NN];
__device__ int   g_rowptr[NN + 1];
__device__ int   g_fill[NN];
__device__ int   g_csrc[NE];

__device__ __forceinline__ float lrelu(float x) {
    return x > 0.0f ? x : NEG_SLOPE * x;
}

// ================= CSR build =================
__global__ void k_zero_cnt() {
    int i = blockIdx.x * blockDim.x + threadIdx.x;
    if (i < NN) g_cnt[i] = 0;
}

__global__ void k_count(const int* __restrict__ dst) {
    int e = blockIdx.x * blockDim.x + threadIdx.x;
    if (e < NE) atomicAdd(&g_cnt[dst[e]], 1);
}

// single-block exclusive scan over 50000 counts -> rowptr, fill
__global__ void k_scan() {
    __shared__ int warpsum[32];
    const int T = 1024;
    const int CH = (NN + T - 1) / T;  // 49
    int t = threadIdx.x;
    int lane = t & 31, wid = t >> 5;
    int lo = t * CH;
    int hi = lo + CH; if (hi > NN) hi = NN;
    if (lo > NN) lo = NN;
    int s = 0;
    for (int i = lo; i < hi; i++) s += g_cnt[i];
    // inclusive warp scan of s
    int v = s;
#pragma unroll
    for (int o = 1; o < 32; o <<= 1) {
        int u = __shfl_up_sync(0xFFFFFFFFu, v, o);
        if (lane >= o) v += u;
    }
    if (lane == 31) warpsum[wid] = v;
    __syncthreads();
    if (wid == 0) {
        int w = (lane < 32) ? warpsum[lane] : 0;
#pragma unroll
        for (int o = 1; o < 32; o <<= 1) {
            int u = __shfl_up_sync(0xFFFFFFFFu, w, o);
            if (lane >= o) w += u;
        }
        warpsum[lane] = w;
    }
    __syncthreads();
    int excl = v - s + (wid > 0 ? warpsum[wid - 1] : 0);
    int run = excl;
    for (int i = lo; i < hi; i++) {
        g_rowptr[i] = run;
        g_fill[i] = run;
        run += g_cnt[i];
    }
    if (t == T - 1) g_rowptr[NN] = run;
}

__global__ void k_fill(const int* __restrict__ src, const int* __restrict__ dst) {
    int e = blockIdx.x * blockDim.x + threadIdx.x;
    if (e >= NE) return;
    int pos = atomicAdd(&g_fill[dst[e]], 1);
    g_csrc[pos] = src[e];
}

// ================= SGEMM 128x128x32, 8x8 per thread =================
// C[M,N] = A[M,K] @ B[K,N] (+bias); requires K%32==0, N%128==0.
__global__ void sgemm128(const float* __restrict__ A, const float* __restrict__ B,
                         const float* __restrict__ bias, float* __restrict__ C,
                         int M, int N, int K) {
    const int BM = 128, BN = 128, BK = 32;
    __shared__ float As[BK][BM + 4];
    __shared__ float Bs[BK][BN + 4];
    const int tid = threadIdx.x;         // 256
    const int tx = tid & 15;             // col group
    const int ty = tid >> 4;             // row group
    const int rowBase = blockIdx.y * BM;
    const int colBase = blockIdx.x * BN;

    float acc[8][8];
#pragma unroll
    for (int i = 0; i < 8; i++)
#pragma unroll
        for (int j = 0; j < 8; j++) acc[i][j] = 0.0f;

    for (int k0 = 0; k0 < K; k0 += BK) {
        // load A tile (BM x BK) transposed into As
#pragma unroll
        for (int j = 0; j < 4; j++) {
            int f = tid + j * 256;          // 0..1023 float4 slots
            int r = f >> 3;                 // 0..127
            int c4 = (f & 7) << 2;          // 0,4,...,28
            int gr = rowBase + r;
            float4 a4 = make_float4(0.f, 0.f, 0.f, 0.f);
            if (gr < M) a4 = *(const float4*)(A + (size_t)gr * K + k0 + c4);
            As[c4 + 0][r] = a4.x;
            As[c4 + 1][r] = a4.y;
            As[c4 + 2][r] = a4.z;
            As[c4 + 3][r] = a4.w;
        }
        // load B tile (BK x BN)
#pragma unroll
        for (int j = 0; j < 4; j++) {
            int f = tid + j * 256;
            int kk = f >> 5;                // 0..31
            int c4 = (f & 31) << 2;         // 0..124
            *(float4*)(&Bs[kk][c4]) = *(const float4*)(B + (size_t)(k0 + kk) * N + colBase + c4);
        }
        __syncthreads();
#pragma unroll
        for (int kk = 0; kk < BK; kk++) {
            float a[8], b[8];
            *(float4*)(a)     = *(float4*)(&As[kk][ty * 8]);
            *(float4*)(a + 4) = *(float4*)(&As[kk][ty * 8 + 4]);
            *(float4*)(b)     = *(float4*)(&Bs[kk][tx * 8]);
            *(float4*)(b + 4) = *(float4*)(&Bs[kk][tx * 8 + 4]);
#pragma unroll
            for (int i = 0; i < 8; i++)
#pragma unroll
                for (int j = 0; j < 8; j++)
                    acc[i][j] = fmaf(a[i], b[j], acc[i][j]);
        }
        __syncthreads();
    }

#pragma unroll
    for (int i = 0; i < 8; i++) {
        int row = rowBase + ty * 8 + i;
        if (row >= M) continue;
#pragma unroll
        for (int j4 = 0; j4 < 2; j4++) {
            int col = colBase + tx * 8 + j4 * 4;
            float4 v;
            v.x = acc[i][j4 * 4 + 0];
            v.y = acc[i][j4 * 4 + 1];
            v.z = acc[i][j4 * 4 + 2];
            v.w = acc[i][j4 * 4 + 3];
            if (bias) {
                v.x += bias[col + 0]; v.y += bias[col + 1];
                v.z += bias[col + 2]; v.w += bias[col + 3];
            }
            *(float4*)(C + (size_t)row * N + col) = v;
        }
    }
}

// ================= attention coefficients =================
__global__ void k_attn_coef(const float* __restrict__ al, const float* __restrict__ ar) {
    int n = blockIdx.x;
    int d = threadIdx.x;                  // 0..127
    float w = g_Wh[n * DHID + d];
    float pl = w * al[d];
    float pr = w * ar[d];
#pragma unroll
    for (int o = 16; o > 0; o >>= 1) {
        pl += __shfl_down_sync(0xFFFFFFFFu, pl, o);
        pr += __shfl_down_sync(0xFFFFFFFFu, pr, o);
    }
    if ((d & 31) == 0) {
        int h = d >> 5;
        g_el[n * NH + h] = pl;
        g_er[n * NH + h] = pr;
    }
}

// ================= fused softmax + aggregate (warp per node) =================
// LAYER==1: out = elu(agg + b) -> g_z   [NN,128]
// LAYER==2: out = mean_heads(agg + b) -> g_z2  [NN,32]
template <int LAYER>
__global__ void k_gat_agg(const float* __restrict__ bias) {
    int n = (blockIdx.x << 3) + (threadIdx.x >> 5);
    if (n >= NN) return;
    int lane = threadIdx.x & 31;
    int beg = g_rowptr[n], end = g_rowptr[n + 1];
    float4 er4 = *(const float4*)(g_er + n * NH);

    // pass 1: per-head max (warp-parallel over edges)
    float m0 = -INFINITY, m1 = -INFINITY, m2 = -INFINITY, m3 = -INFINITY;
    for (int i = beg + lane; i < end; i += 32) {
        int s = g_csrc[i];
        float4 el = *(const float4*)(g_el + s * NH);
        m0 = fmaxf(m0, lrelu(el.x + er4.x));
        m1 = fmaxf(m1, lrelu(el.y + er4.y));
        m2 = fmaxf(m2, lrelu(el.z + er4.z));
        m3 = fmaxf(m3, lrelu(el.w + er4.w));
    }
#pragma unroll
    for (int o = 16; o > 0; o >>= 1) {
        m0 = fmaxf(m0, __shfl_xor_sync(0xFFFFFFFFu, m0, o));
        m1 = fmaxf(m1, __shfl_xor_sync(0xFFFFFFFFu, m1, o));
        m2 = fmaxf(m2, __shfl_xor_sync(0xFFFFFFFFu, m2, o));
        m3 = fmaxf(m3, __shfl_xor_sync(0xFFFFFFFFu, m3, o));
    }

    // pass 2: serial over edges, all 32 lanes cooperate per edge
    int myh = lane >> 3;                 // head owned by this lane's dims
    float ax = 0.f, ay = 0.f, az = 0.f, aw = 0.f;
    float se0 = 0.f, se1 = 0.f, se2 = 0.f, se3 = 0.f;
    const float* WhBase = g_Wh + (size_t)lane * 4;
    for (int i = beg; i < end; i++) {
        int s = g_csrc[i];               // uniform -> broadcast
        float4 el = *(const float4*)(g_el + s * NH);
        float ex0 = __expf(lrelu(el.x + er4.x) - m0);
        float ex1 = __expf(lrelu(el.y + er4.y) - m1);
        float ex2 = __expf(lrelu(el.z + er4.z) - m2);
        float ex3 = __expf(lrelu(el.w + er4.w) - m3);
        se0 += ex0; se1 += ex1; se2 += ex2; se3 += ex3;
        float exh = (myh == 0) ? ex0 : (myh == 1) ? ex1 : (myh == 2) ? ex2 : ex3;
        float4 w = *(const float4*)(WhBase + (size_t)s * DHID);
        ax = fmaf(exh, w.x, ax);
        ay = fmaf(exh, w.y, ay);
        az = fmaf(exh, w.z, az);
        aw = fmaf(exh, w.w, aw);
    }
    float seh = (myh == 0) ? se0 : (myh == 1) ? se1 : (myh == 2) ? se2 : se3;
    float r = 1.0f / (seh + EPSV);
    ax *= r; ay *= r; az *= r; aw *= r;

    if (LAYER == 1) {
        int d = lane * 4;
        float4 v;
        v.x = ax + bias[d + 0];
        v.y = ay + bias[d + 1];
        v.z = az + bias[d + 2];
        v.w = aw + bias[d + 3];
        v.x = v.x > 0.f ? v.x : (__expf(v.x) - 1.0f);
        v.y = v.y > 0.f ? v.y : (__expf(v.y) - 1.0f);
        v.z = v.z > 0.f ? v.z : (__expf(v.z) - 1.0f);
        v.w = v.w > 0.f ? v.w : (__expf(v.w) - 1.0f);
        *(float4*)(g_z + (size_t)n * DHID + d) = v;
    } else {
        int d = lane * 4;                 // global dim; add bias first
        ax += bias[d + 0]; ay += bias[d + 1]; az += bias[d + 2]; aw += bias[d + 3];
        // sum across the 4 heads: lanes L, L+8, L+16, L+24 hold same local dim
#pragma unroll
        for (int o = 8; o <= 16; o <<= 1) {
            ax += __shfl_xor_sync(0xFFFFFFFFu, ax, o);
            ay += __shfl_xor_sync(0xFFFFFFFFu, ay, o);
            az += __shfl_xor_sync(0xFFFFFFFFu, az, o);
            aw += __shfl_xor_sync(0xFFFFFFFFu, aw, o);
        }
        if (lane < 8) {
            float4 v = make_float4(0.25f * ax, 0.25f * ay, 0.25f * az, 0.25f * aw);
            *(float4*)(g_z2 + (size_t)n * DHEAD + lane * 4) = v;
        }
    }
}

// ================= launch =================
extern "C" void kernel_launch(void* const* d_in, const int* in_sizes, int n_in,
                              void* d_out, int out_size) {
    const float* h   = (const float*)d_in[0];
    const int*   src = (const int*)d_in[1];
    const int*   dst = (const int*)d_in[2];
    const float* W1  = (const float*)d_in[3];
    const float* al1 = (const float*)d_in[4];
    const float* ar1 = (const float*)d_in[5];
    const float* b1  = (const float*)d_in[6];
    const float* W2  = (const float*)d_in[7];
    const float* al2 = (const float*)d_in[8];
    const float* ar2 = (const float*)d_in[9];
    const float* b2  = (const float*)d_in[10];
    const float* Wp  = (const float*)d_in[11];
    const float* bp  = (const float*)d_in[12];
    float* out = (float*)d_out;

    float *p_Wh, *p_z, *p_z2;
    cudaGetSymbolAddress((void**)&p_Wh, g_Wh);
    cudaGetSymbolAddress((void**)&p_z,  g_z);
    cudaGetSymbolAddress((void**)&p_z2, g_z2);

    const int TPB = 256;
    int gN    = (NN + TPB - 1) / TPB;
    int gEdge = (NE + TPB - 1) / TPB;
    int gAgg  = (NN + 7) / 8;

    dim3 gemmGrid1(1, (NN + 127) / 128);            // N=128
    dim3 gemmGridP(OUTD / 128, (NN + 127) / 128);   // N=512

    // ---- CSR build (once; shared by both layers) ----
    k_zero_cnt<<<gN, TPB>>>();
    k_count<<<gEdge, TPB>>>(dst);
    k_scan<<<1, 1024>>>();
    k_fill<<<gEdge, TPB>>>(src, dst);

    // ===== layer 1 =====
    sgemm128<<<gemmGrid1, 256>>>(h, W1, nullptr, p_Wh, NN, DHID, DHID);
    k_attn_coef<<<NN, 128>>>(al1, ar1);
    k_gat_agg<1><<<gAgg, 256>>>(b1);

    // ===== layer 2 =====
    sgemm128<<<gemmGrid1, 256>>>(p_z, W2, nullptr, p_Wh, NN, DHID, DHID);
    k_attn_coef<<<NN, 128>>>(al2, ar2);
    k_gat_agg<2><<<gAgg, 256>>>(b2);

    // ===== projection head =====
    sgemm128<<<gemmGridP, 256>>>(p_z2, Wp, bp, out, NN, OUTD, DHEAD);
}

// round 3
// speedup vs baseline: 2.5822x; 1.4107x over previous
#include <cuda_runtime.h>
#include <math.h>

#define NN 50000
#define NE 800000
#define DHID 128
#define NH 4
#define DHEAD 32
#define OUTD 512
#define NEG_SLOPE 0.2f
#define EPSV 1e-9f

// ---------------- scratch (device globals; no allocation) ----------------
__device__ float g_Wh[NN * DHID];
__device__ float g_z[NN * DHID];
__device__ float g_el[NN * NH];
__device__ float g_er[NN * NH];
__device__ float g_z2[NN * DHEAD];
__device__ int   g_cnt[NN];
__device__ int   g_rowptr[NN + 1];
__device__ int   g_epos[NE];
__device__ int   g_csrc[NE];

__device__ __forceinline__ float lrelu(float x) {
    return x > 0.0f ? x : NEG_SLOPE * x;
}

// ================= CSR build =================
__global__ void k_count(const int* __restrict__ dst) {
    int e = blockIdx.x * blockDim.x + threadIdx.x;
    if (e < NE) g_epos[e] = atomicAdd(&g_cnt[dst[e]], 1);
}

// single-block exclusive scan over 50000 counts -> rowptr
__global__ void k_scan() {
    __shared__ int warpsum[32];
    const int T = 1024;
    const int CH = (NN + T - 1) / T;  // 49
    int t = threadIdx.x;
    int lane = t & 31, wid = t >> 5;
    int lo = t * CH;
    int hi = lo + CH; if (hi > NN) hi = NN;
    if (lo > NN) lo = NN;
    int s = 0;
    for (int i = lo; i < hi; i++) s += g_cnt[i];
    int v = s;
#pragma unroll
    for (int o = 1; o < 32; o <<= 1) {
        int u = __shfl_up_sync(0xFFFFFFFFu, v, o);
        if (lane >= o) v += u;
    }
    if (lane == 31) warpsum[wid] = v;
    __syncthreads();
    if (wid == 0) {
        int w = warpsum[lane];
#pragma unroll
        for (int o = 1; o < 32; o <<= 1) {
            int u = __shfl_up_sync(0xFFFFFFFFu, w, o);
            if (lane >= o) w += u;
        }
        warpsum[lane] = w;
    }
    __syncthreads();
    int excl = v - s + (wid > 0 ? warpsum[wid - 1] : 0);
    int run = excl;
    for (int i = lo; i < hi; i++) {
        g_rowptr[i] = run;
        run += g_cnt[i];
    }
    if (t == T - 1) g_rowptr[NN] = run;
}

__global__ void k_fill(const int* __restrict__ src, const int* __restrict__ dst) {
    int e = blockIdx.x * blockDim.x + threadIdx.x;
    if (e >= NE) return;
    int t = dst[e];
    g_csrc[g_rowptr[t] + g_epos[e]] = src[e];
}

// ================= pipelined SGEMM 128x128x8, 8x8/thread =================
// FUSE=1: additionally computes g_el/g_er from the C tile (requires grid.x==1, N==128)
template <int FUSE>
__global__ void __launch_bounds__(256, 2)
sgemm_pipe(const float* __restrict__ A, const float* __restrict__ B,
           const float* __restrict__ bias, float* __restrict__ C,
           int M, int N, int K,
           const float* __restrict__ al, const float* __restrict__ ar) {
    __shared__ float As[2][8][132];
    __shared__ float Bs[2][8][132];
    const int tid = threadIdx.x;
    const int tx = tid & 15, ty = tid >> 4;
    const int rowBase = blockIdx.y * 128;
    const int colBase = blockIdx.x * 128;

    const int arow = tid >> 1;            // 0..127
    const int akq  = (tid & 1) * 4;       // 0 or 4
    const int bk   = tid >> 5;            // 0..7
    const int bc   = (tid & 31) * 4;      // 0..124

    float acc[8][8];
#pragma unroll
    for (int i = 0; i < 8; i++)
#pragma unroll
        for (int j = 0; j < 8; j++) acc[i][j] = 0.0f;

    // preload tile 0
    {
        int gr = rowBase + arow;
        float4 a4 = make_float4(0.f, 0.f, 0.f, 0.f);
        if (gr < M) a4 = *(const float4*)(A + (size_t)gr * K + akq);
        As[0][akq + 0][arow] = a4.x; As[0][akq + 1][arow] = a4.y;
        As[0][akq + 2][arow] = a4.z; As[0][akq + 3][arow] = a4.w;
        float4 b4 = *(const float4*)(B + (size_t)bk * N + colBase + bc);
        *(float4*)&Bs[0][bk][bc] = b4;
    }
    __syncthreads();

    int cur = 0;
    for (int k0 = 0; k0 < K; k0 += 8) {
        float4 a4, b4;
        const bool hn = (k0 + 8) < K;
        if (hn) {
            int gr = rowBase + arow;
            a4 = make_float4(0.f, 0.f, 0.f, 0.f);
            if (gr < M) a4 = *(const float4*)(A + (size_t)gr * K + (k0 + 8) + akq);
            b4 = *(const float4*)(B + (size_t)(k0 + 8 + bk) * N + colBase + bc);
        }
#pragma unroll
        for (int kk = 0; kk < 8; kk++) {
            float a[8], b[8];
            *(float4*)(a)     = *(float4*)&As[cur][kk][ty * 8];
            *(float4*)(a + 4) = *(float4*)&As[cur][kk][ty * 8 + 4];
            *(float4*)(b)     = *(float4*)&Bs[cur][kk][tx * 8];
            *(float4*)(b + 4) = *(float4*)&Bs[cur][kk][tx * 8 + 4];
#pragma unroll
            for (int i = 0; i < 8; i++)
#pragma unroll
                for (int j = 0; j < 8; j++)
                    acc[i][j] = fmaf(a[i], b[j], acc[i][j]);
        }
        if (hn) {
            As[cur ^ 1][akq + 0][arow] = a4.x; As[cur ^ 1][akq + 1][arow] = a4.y;
            As[cur ^ 1][akq + 2][arow] = a4.z; As[cur ^ 1][akq + 3][arow] = a4.w;
            *(float4*)&Bs[cur ^ 1][bk][bc] = b4;
        }
        __syncthreads();
        cur ^= 1;
    }

    // store C
#pragma unroll
    for (int i = 0; i < 8; i++) {
        int row = rowBase + ty * 8 + i;
        if (row >= M) continue;
#pragma unroll
        for (int j4 = 0; j4 < 2; j4++) {
            int col = colBase + tx * 8 + j4 * 4;
            float4 v;
            v.x = acc[i][j4 * 4 + 0]; v.y = acc[i][j4 * 4 + 1];
            v.z = acc[i][j4 * 4 + 2]; v.w = acc[i][j4 * 4 + 3];
            if (!FUSE && bias) {
                v.x += bias[col + 0]; v.y += bias[col + 1];
                v.z += bias[col + 2]; v.w += bias[col + 3];
            }
            *(float4*)(C + (size_t)row * N + col) = v;
        }
    }

    if (FUSE) {
        // el[n,h] = sum_d Wh[n, h*32+d]*al[h*32+d]; block owns full row (N=128)
        float alv[8], arv[8];
#pragma unroll
        for (int j = 0; j < 8; j++) {
            alv[j] = al[tx * 8 + j];
            arv[j] = ar[tx * 8 + j];
        }
        float* redl = &As[0][0][0];   // reuse smem: 2048 floats needed, 2112 avail
        float* redr = &Bs[0][0][0];
#pragma unroll
        for (int i = 0; i < 8; i++) {
            float pl = 0.f, pr = 0.f;
#pragma unroll
            for (int j = 0; j < 8; j++) {
                pl = fmaf(acc[i][j], alv[j], pl);
                pr = fmaf(acc[i][j], arv[j], pr);
            }
            redl[(ty * 8 + i) * 16 + tx] = pl;
            redr[(ty * 8 + i) * 16 + tx] = pr;
        }
        __syncthreads();
        for (int p = tid; p < 512; p += 256) {
            int row = p >> 2, hh = p & 3;
            int gr = rowBase + row;
            if (gr < M) {
                int b0 = row * 16 + hh * 4;
                float sl = redl[b0] + redl[b0 + 1] + redl[b0 + 2] + redl[b0 + 3];
                float sr = redr[b0] + redr[b0 + 1] + redr[b0 + 2] + redr[b0 + 3];
                g_el[gr * NH + hh] = sl;
                g_er[gr * NH + hh] = sr;
            }
        }
    }
}

// ================= fused softmax + aggregate (warp per node, no max pass) ====
// LAYER==1: out = elu(agg + b) -> g_z   [NN,128]
// LAYER==2: out = mean_heads(agg + b) -> g_z2  [NN,32]
template <int LAYER>
__global__ void k_gat_agg(const float* __restrict__ bias) {
    int n = (blockIdx.x << 3) + (threadIdx.x >> 5);
    if (n >= NN) return;
    int lane = threadIdx.x & 31;
    int myh = lane >> 3;
    int beg = g_rowptr[n], end = g_rowptr[n + 1];
    float4 er4 = *(const float4*)(g_er + n * NH);

    float ax = 0.f, ay = 0.f, az = 0.f, aw = 0.f;
    float se0 = 0.f, se1 = 0.f, se2 = 0.f, se3 = 0.f;
    const float* WhBase = g_Wh + (size_t)(lane * 4);

    for (int base = beg; base < end; base += 32) {
        int cnt = end - base; if (cnt > 32) cnt = 32;
        int sv = 0;
        float4 elv = make_float4(0.f, 0.f, 0.f, 0.f);
        if (lane < cnt) {
            sv = g_csrc[base + lane];
            elv = *(const float4*)(g_el + sv * NH);
        }
        float e0 = __expf(lrelu(elv.x + er4.x));
        float e1 = __expf(lrelu(elv.y + er4.y));
        float e2 = __expf(lrelu(elv.z + er4.z));
        float e3 = __expf(lrelu(elv.w + er4.w));
        if (lane >= cnt) { e0 = e1 = e2 = e3 = 0.f; }
        se0 += e0; se1 += e1; se2 += e2; se3 += e3;
#pragma unroll 4
        for (int j = 0; j < cnt; j++) {
            int s    = __shfl_sync(0xFFFFFFFFu, sv, j);
            float q0 = __shfl_sync(0xFFFFFFFFu, e0, j);
            float q1 = __shfl_sync(0xFFFFFFFFu, e1, j);
            float q2 = __shfl_sync(0xFFFFFFFFu, e2, j);
            float q3 = __shfl_sync(0xFFFFFFFFu, e3, j);
            float exh = myh < 2 ? (myh == 0 ? q0 : q1) : (myh == 2 ? q2 : q3);
            float4 w = *(const float4*)(WhBase + (size_t)s * DHID);
            ax = fmaf(exh, w.x, ax);
            ay = fmaf(exh, w.y, ay);
            az = fmaf(exh, w.z, az);
            aw = fmaf(exh, w.w, aw);
        }
    }
#pragma unroll
    for (int o = 16; o > 0; o >>= 1) {
        se0 += __shfl_xor_sync(0xFFFFFFFFu, se0, o);
        se1 += __shfl_xor_sync(0xFFFFFFFFu, se1, o);
        se2 += __shfl_xor_sync(0xFFFFFFFFu, se2, o);
        se3 += __shfl_xor_sync(0xFFFFFFFFu, se3, o);
    }
    float seh = myh < 2 ? (myh == 0 ? se0 : se1) : (myh == 2 ? se2 : se3);
    float r = 1.0f / (seh + EPSV);
    ax *= r; ay *= r; az *= r; aw *= r;

    if (LAYER == 1) {
        int d = lane * 4;
        float4 v;
        v.x = ax + bias[d + 0];
        v.y = ay + bias[d + 1];
        v.z = az + bias[d + 2];
        v.w = aw + bias[d + 3];
        v.x = v.x > 0.f ? v.x : (__expf(v.x) - 1.0f);
        v.y = v.y > 0.f ? v.y : (__expf(v.y) - 1.0f);
        v.z = v.z > 0.f ? v.z : (__expf(v.z) - 1.0f);
        v.w = v.w > 0.f ? v.w : (__expf(v.w) - 1.0f);
        *(float4*)(g_z + (size_t)n * DHID + d) = v;
    } else {
        int d = lane * 4;
        ax += bias[d + 0]; ay += bias[d + 1]; az += bias[d + 2]; aw += bias[d + 3];
#pragma unroll
        for (int o = 8; o <= 16; o <<= 1) {
            ax += __shfl_xor_sync(0xFFFFFFFFu, ax, o);
            ay += __shfl_xor_sync(0xFFFFFFFFu, ay, o);
            az += __shfl_xor_sync(0xFFFFFFFFu, az, o);
            aw += __shfl_xor_sync(0xFFFFFFFFu, aw, o);
        }
        if (lane < 8) {
            float4 v = make_float4(0.25f * ax, 0.25f * ay, 0.25f * az, 0.25f * aw);
            *(float4*)(g_z2 + (size_t)n * DHEAD + lane * 4) = v;
        }
    }
}

// ================= launch =================
extern "C" void kernel_launch(void* const* d_in, const int* in_sizes, int n_in,
                              void* d_out, int out_size) {
    const float* h   = (const float*)d_in[0];
    const int*   src = (const int*)d_in[1];
    const int*   dst = (const int*)d_in[2];
    const float* W1  = (const float*)d_in[3];
    const float* al1 = (const float*)d_in[4];
    const float* ar1 = (const float*)d_in[5];
    const float* b1  = (const float*)d_in[6];
    const float* W2  = (const float*)d_in[7];
    const float* al2 = (const float*)d_in[8];
    const float* ar2 = (const float*)d_in[9];
    const float* b2  = (const float*)d_in[10];
    const float* Wp  = (const float*)d_in[11];
    const float* bp  = (const float*)d_in[12];
    float* out = (float*)d_out;

    float *p_Wh, *p_z, *p_z2;
    int *p_cnt;
    cudaGetSymbolAddress((void**)&p_Wh,  g_Wh);
    cudaGetSymbolAddress((void**)&p_z,   g_z);
    cudaGetSymbolAddress((void**)&p_z2,  g_z2);
    cudaGetSymbolAddress((void**)&p_cnt, g_cnt);

    const int TPB = 256;
    int gEdge = (NE + TPB - 1) / TPB;
    int gAgg  = (NN + 7) / 8;

    dim3 gemmGrid1(1, (NN + 127) / 128);            // N=128
    dim3 gemmGridP(OUTD / 128, (NN + 127) / 128);   // N=512

    // ---- CSR build (shared by both layers) ----
    cudaMemsetAsync(p_cnt, 0, NN * sizeof(int), 0);
    k_count<<<gEdge, TPB>>>(dst);
    k_scan<<<1, 1024>>>();
    k_fill<<<gEdge, TPB>>>(src, dst);

    // ===== layer 1 =====
    sgemm_pipe<1><<<gemmGrid1, 256>>>(h, W1, nullptr, p_Wh, NN, DHID, DHID, al1, ar1);
    k_gat_agg<1><<<gAgg, 256>>>(b1);

    // ===== layer 2 =====
    sgemm_pipe<1><<<gemmGrid1, 256>>>(p_z, W2, nullptr, p_Wh, NN, DHID, DHID, al2, ar2);
    k_gat_agg<2><<<gAgg, 256>>>(b2);

    // ===== projection head =====
    sgemm_pipe<0><<<gemmGridP, 256>>>(p_z2, Wp, bp, out, NN, OUTD, DHEAD, nullptr, nullptr);
}

// round 4
// speedup vs baseline: 2.8051x; 1.0863x over previous
#include <cuda_runtime.h>
#include <cuda_fp16.h>
#include <math.h>

#define NN 50000
#define NE 800000
#define DHID 128
#define NH 4
#define DHEAD 32
#define OUTD 512
#define NEG_SLOPE 0.2f
#define EPSV 1e-9f

// ---------------- scratch (device globals; no allocation) ----------------
__device__ __half g_Whh[NN * DHID];   // fp16 message payload
__device__ float g_z[NN * DHID];
__device__ float g_el[NN * NH];
__device__ float g_er[NN * NH];
__device__ float g_z2[NN * DHEAD];
__device__ int   g_cnt[NN];
__device__ int   g_rowptr[NN + 1];
__device__ int   g_epos[NE];
__device__ int   g_csrc[NE];

__device__ __forceinline__ float lrelu(float x) {
    return x > 0.0f ? x : NEG_SLOPE * x;
}

// ---------------- streams/events for fork-join (host resources, created once) ----
static cudaStream_t g_s2;
static cudaEvent_t g_evFork, g_evCsr;
struct HostInit {
    HostInit() {
        cudaStreamCreateWithFlags(&g_s2, cudaStreamNonBlocking);
        cudaEventCreateWithFlags(&g_evFork, cudaEventDisableTiming);
        cudaEventCreateWithFlags(&g_evCsr, cudaEventDisableTiming);
    }
};
static HostInit g_hostInit;

// ================= CSR build =================
__global__ void k_count(const int* __restrict__ dst) {
    int e = blockIdx.x * blockDim.x + threadIdx.x;
    if (e < NE) g_epos[e] = atomicAdd(&g_cnt[dst[e]], 1);
}

// single-block exclusive scan over 50000 counts -> rowptr
__global__ void k_scan() {
    __shared__ int warpsum[32];
    const int T = 1024;
    const int CH = (NN + T - 1) / T;  // 49
    int t = threadIdx.x;
    int lane = t & 31, wid = t >> 5;
    int lo = t * CH;
    int hi = lo + CH; if (hi > NN) hi = NN;
    if (lo > NN) lo = NN;
    int s = 0;
    for (int i = lo; i < hi; i++) s += g_cnt[i];
    int v = s;
#pragma unroll
    for (int o = 1; o < 32; o <<= 1) {
        int u = __shfl_up_sync(0xFFFFFFFFu, v, o);
        if (lane >= o) v += u;
    }
    if (lane == 31) warpsum[wid] = v;
    __syncthreads();
    if (wid == 0) {
        int w = warpsum[lane];
#pragma unroll
        for (int o = 1; o < 32; o <<= 1) {
            int u = __shfl_up_sync(0xFFFFFFFFu, w, o);
            if (lane >= o) w += u;
        }
        warpsum[lane] = w;
    }
    __syncthreads();
    int excl = v - s + (wid > 0 ? warpsum[wid - 1] : 0);
    int run = excl;
    for (int i = lo; i < hi; i++) {
        g_rowptr[i] = run;
        run += g_cnt[i];
    }
    if (t == T - 1) g_rowptr[NN] = run;
}

__global__ void k_fill(const int* __restrict__ src, const int* __restrict__ dst) {
    int e = blockIdx.x * blockDim.x + threadIdx.x;
    if (e >= NE) return;
    int t = dst[e];
    g_csrc[g_rowptr[t] + g_epos[e]] = src[e];
}

// ================= pipelined SGEMM 128x128x8, 8x8/thread =================
// FUSE=1: writes fp16 g_Whh and computes g_el/g_er (requires grid.x==1, N==128);
//         fp32 C is NOT written.
// FUSE=0: writes fp32 C (+bias).
template <int FUSE>
__global__ void __launch_bounds__(256, 2)
sgemm_pipe(const float* __restrict__ A, const float* __restrict__ B,
           const float* __restrict__ bias, float* __restrict__ C,
           int M, int N, int K,
           const float* __restrict__ al, const float* __restrict__ ar) {
    __shared__ float As[2][8][132];
    __shared__ float Bs[2][8][132];
    const int tid = threadIdx.x;
    const int tx = tid & 15, ty = tid >> 4;
    const int rowBase = blockIdx.y * 128;
    const int colBase = blockIdx.x * 128;

    const int arow = tid >> 1;            // 0..127
    const int akq  = (tid & 1) * 4;       // 0 or 4
    const int bk   = tid >> 5;            // 0..7
    const int bc   = (tid & 31) * 4;      // 0..124

    float acc[8][8];
#pragma unroll
    for (int i = 0; i < 8; i++)
#pragma unroll
        for (int j = 0; j < 8; j++) acc[i][j] = 0.0f;

    // preload tile 0
    {
        int gr = rowBase + arow;
        float4 a4 = make_float4(0.f, 0.f, 0.f, 0.f);
        if (gr < M) a4 = *(const float4*)(A + (size_t)gr * K + akq);
        As[0][akq + 0][arow] = a4.x; As[0][akq + 1][arow] = a4.y;
        As[0][akq + 2][arow] = a4.z; As[0][akq + 3][arow] = a4.w;
        float4 b4 = *(const float4*)(B + (size_t)bk * N + colBase + bc);
        *(float4*)&Bs[0][bk][bc] = b4;
    }
    __syncthreads();

    int cur = 0;
    for (int k0 = 0; k0 < K; k0 += 8) {
        float4 a4, b4;
        const bool hn = (k0 + 8) < K;
        if (hn) {
            int gr = rowBase + arow;
            a4 = make_float4(0.f, 0.f, 0.f, 0.f);
            if (gr < M) a4 = *(const float4*)(A + (size_t)gr * K + (k0 + 8) + akq);
            b4 = *(const float4*)(B + (size_t)(k0 + 8 + bk) * N + colBase + bc);
        }
#pragma unroll
        for (int kk = 0; kk < 8; kk++) {
            float a[8], b[8];
            *(float4*)(a)     = *(float4*)&As[cur][kk][ty * 8];
            *(float4*)(a + 4) = *(float4*)&As[cur][kk][ty * 8 + 4];
            *(float4*)(b)     = *(float4*)&Bs[cur][kk][tx * 8];
            *(float4*)(b + 4) = *(float4*)&Bs[cur][kk][tx * 8 + 4];
#pragma unroll
            for (int i = 0; i < 8; i++)
#pragma unroll
                for (int j = 0; j < 8; j++)
                    acc[i][j] = fmaf(a[i], b[j], acc[i][j]);
        }
        if (hn) {
            As[cur ^ 1][akq + 0][arow] = a4.x; As[cur ^ 1][akq + 1][arow] = a4.y;
            As[cur ^ 1][akq + 2][arow] = a4.z; As[cur ^ 1][akq + 3][arow] = a4.w;
            *(float4*)&Bs[cur ^ 1][bk][bc] = b4;
        }
        __syncthreads();
        cur ^= 1;
    }

    if (!FUSE) {
        // store fp32 C (+bias)
#pragma unroll
        for (int i = 0; i < 8; i++) {
            int row = rowBase + ty * 8 + i;
            if (row >= M) continue;
#pragma unroll
            for (int j4 = 0; j4 < 2; j4++) {
                int col = colBase + tx * 8 + j4 * 4;
                float4 v;
                v.x = acc[i][j4 * 4 + 0]; v.y = acc[i][j4 * 4 + 1];
                v.z = acc[i][j4 * 4 + 2]; v.w = acc[i][j4 * 4 + 3];
                if (bias) {
                    v.x += bias[col + 0]; v.y += bias[col + 1];
                    v.z += bias[col + 2]; v.w += bias[col + 3];
                }
                *(float4*)(C + (size_t)row * N + col) = v;
            }
        }
    } else {
        // fp16 message payload store
#pragma unroll
        for (int i = 0; i < 8; i++) {
            int row = rowBase + ty * 8 + i;
            if (row >= M) continue;
            __half2 hp[4];
#pragma unroll
            for (int j = 0; j < 4; j++)
                hp[j] = __floats2half2_rn(acc[i][j * 2], acc[i][j * 2 + 1]);
            *(uint4*)(g_Whh + (size_t)row * DHID + tx * 8) = *(uint4*)hp;
        }

        // el/er from fp32 accumulators
        float alv[8], arv[8];
#pragma unroll
        for (int j = 0; j < 8; j++) {
            alv[j] = al[tx * 8 + j];
            arv[j] = ar[tx * 8 + j];
        }
        float* redl = &As[0][0][0];
        float* redr = &Bs[0][0][0];
#pragma unroll
        for (int i = 0; i < 8; i++) {
            float pl = 0.f, pr = 0.f;
#pragma unroll
            for (int j = 0; j < 8; j++) {
                pl = fmaf(acc[i][j], alv[j], pl);
                pr = fmaf(acc[i][j], arv[j], pr);
            }
            redl[(ty * 8 + i) * 16 + tx] = pl;
            redr[(ty * 8 + i) * 16 + tx] = pr;
        }
        __syncthreads();
        for (int p = tid; p < 512; p += 256) {
            int row = p >> 2, hh = p & 3;
            int gr = rowBase + row;
            if (gr < M) {
                int b0 = row * 16 + hh * 4;
                float sl = redl[b0] + redl[b0 + 1] + redl[b0 + 2] + redl[b0 + 3];
                float sr = redr[b0] + redr[b0 + 1] + redr[b0 + 2] + redr[b0 + 3];
                g_el[gr * NH + hh] = sl;
                g_er[gr * NH + hh] = sr;
            }
        }
    }
}

// ================= fused softmax + aggregate (warp per node, no max pass) ====
// LAYER==1: out = elu(agg + b) -> g_z   [NN,128]
// LAYER==2: out = mean_heads(agg + b) -> g_z2  [NN,32]
template <int LAYER>
__global__ void k_gat_agg(const float* __restrict__ bias) {
    int n = (blockIdx.x << 3) + (threadIdx.x >> 5);
    if (n >= NN) return;
    int lane = threadIdx.x & 31;
    int myh = lane >> 3;
    int beg = g_rowptr[n], end = g_rowptr[n + 1];
    float4 er4 = *(const float4*)(g_er + n * NH);

    float ax = 0.f, ay = 0.f, az = 0.f, aw = 0.f;
    float se0 = 0.f, se1 = 0.f, se2 = 0.f, se3 = 0.f;
    const __half* WhBase = g_Whh + (size_t)(lane * 4);

    for (int base = beg; base < end; base += 32) {
        int cnt = end - base; if (cnt > 32) cnt = 32;
        int sv = 0;
        float4 elv = make_float4(0.f, 0.f, 0.f, 0.f);
        if (lane < cnt) {
            sv = g_csrc[base + lane];
            elv = *(const float4*)(g_el + sv * NH);
        }
        float e0 = __expf(lrelu(elv.x + er4.x));
        float e1 = __expf(lrelu(elv.y + er4.y));
        float e2 = __expf(lrelu(elv.z + er4.z));
        float e3 = __expf(lrelu(elv.w + er4.w));
        if (lane >= cnt) { e0 = e1 = e2 = e3 = 0.f; }
        se0 += e0; se1 += e1; se2 += e2; se3 += e3;
#pragma unroll 4
        for (int j = 0; j < cnt; j++) {
            int s    = __shfl_sync(0xFFFFFFFFu, sv, j);
            float q0 = __shfl_sync(0xFFFFFFFFu, e0, j);
            float q1 = __shfl_sync(0xFFFFFFFFu, e1, j);
            float q2 = __shfl_sync(0xFFFFFFFFu, e2, j);
            float q3 = __shfl_sync(0xFFFFFFFFu, e3, j);
            float exh = myh < 2 ? (myh == 0 ? q0 : q1) : (myh == 2 ? q2 : q3);
            uint2 u = *(const uint2*)(WhBase + (size_t)s * DHID);
            float2 f0 = __half22float2(*(__half2*)&u.x);
            float2 f1 = __half22float2(*(__half2*)&u.y);
            ax = fmaf(exh, f0.x, ax);
            ay = fmaf(exh, f0.y, ay);
            az = fmaf(exh, f1.x, az);
            aw = fmaf(exh, f1.y, aw);
        }
    }
#pragma unroll
    for (int o = 16; o > 0; o >>= 1) {
        se0 += __shfl_xor_sync(0xFFFFFFFFu, se0, o);
        se1 += __shfl_xor_sync(0xFFFFFFFFu, se1, o);
        se2 += __shfl_xor_sync(0xFFFFFFFFu, se2, o);
        se3 += __shfl_xor_sync(0xFFFFFFFFu, se3, o);
    }
    float seh = myh < 2 ? (myh == 0 ? se0 : se1) : (myh == 2 ? se2 : se3);
    float r = 1.0f / (seh + EPSV);
    ax *= r; ay *= r; az *= r; aw *= r;

    if (LAYER == 1) {
        int d = lane * 4;
        float4 v;
        v.x = ax + bias[d + 0];
        v.y = ay + bias[d + 1];
        v.z = az + bias[d + 2];
        v.w = aw + bias[d + 3];
        v.x = v.x > 0.f ? v.x : (__expf(v.x) - 1.0f);
        v.y = v.y > 0.f ? v.y : (__expf(v.y) - 1.0f);
        v.z = v.z > 0.f ? v.z : (__expf(v.z) - 1.0f);
        v.w = v.w > 0.f ? v.w : (__expf(v.w) - 1.0f);
        *(float4*)(g_z + (size_t)n * DHID + d) = v;
    } else {
        int d = lane * 4;
        ax += bias[d + 0]; ay += bias[d + 1]; az += bias[d + 2]; aw += bias[d + 3];
#pragma unroll
        for (int o = 8; o <= 16; o <<= 1) {
            ax += __shfl_xor_sync(0xFFFFFFFFu, ax, o);
            ay += __shfl_xor_sync(0xFFFFFFFFu, ay, o);
            az += __shfl_xor_sync(0xFFFFFFFFu, az, o);
            aw += __shfl_xor_sync(0xFFFFFFFFu, aw, o);
        }
        if (lane < 8) {
            float4 v = make_float4(0.25f * ax, 0.25f * ay, 0.25f * az, 0.25f * aw);
            *(float4*)(g_z2 + (size_t)n * DHEAD + lane * 4) = v;
        }
    }
}

// ================= launch =================
extern "C" void kernel_launch(void* const* d_in, const int* in_sizes, int n_in,
                              void* d_out, int out_size) {
    const float* h   = (const float*)d_in[0];
    const int*   src = (const int*)d_in[1];
    const int*   dst = (const int*)d_in[2];
    const float* W1  = (const float*)d_in[3];
    const float* al1 = (const float*)d_in[4];
    const float* ar1 = (const float*)d_in[5];
    const float* b1  = (const float*)d_in[6];
    const float* W2  = (const float*)d_in[7];
    const float* al2 = (const float*)d_in[8];
    const float* ar2 = (const float*)d_in[9];
    const float* b2  = (const float*)d_in[10];
    const float* Wp  = (const float*)d_in[11];
    const float* bp  = (const float*)d_in[12];
    float* out = (float*)d_out;

    float *p_z, *p_z2;
    int *p_cnt;
    cudaGetSymbolAddress((void**)&p_z,   g_z);
    cudaGetSymbolAddress((void**)&p_z2,  g_z2);
    cudaGetSymbolAddress((void**)&p_cnt, g_cnt);

    const int TPB = 256;
    int gEdge = (NE + TPB - 1) / TPB;
    int gAgg  = (NN + 7) / 8;

    dim3 gemmGrid1(1, (NN + 127) / 128);            // N=128
    dim3 gemmGridP(OUTD / 128, (NN + 127) / 128);   // N=512

    // ---- fork: CSR build on side stream, GEMM1 on main stream ----
    cudaEventRecord(g_evFork, 0);
    cudaStreamWaitEvent(g_s2, g_evFork, 0);
    cudaMemsetAsync(p_cnt, 0, NN * sizeof(int), g_s2);
    k_count<<<gEdge, TPB, 0, g_s2>>>(dst);
    k_scan<<<1, 1024, 0, g_s2>>>();
    k_fill<<<gEdge, TPB, 0, g_s2>>>(src, dst);
    cudaEventRecord(g_evCsr, g_s2);

    // ===== layer 1 =====
    sgemm_pipe<1><<<gemmGrid1, 256>>>(h, W1, nullptr, nullptr, NN, DHID, DHID, al1, ar1);
    cudaStreamWaitEvent(0, g_evCsr, 0);   // join: agg needs CSR
    k_gat_agg<1><<<gAgg, 256>>>(b1);

    // ===== layer 2 =====
    sgemm_pipe<1><<<gemmGrid1, 256>>>(p_z, W2, nullptr, nullptr, NN, DHID, DHID, al2, ar2);
    k_gat_agg<2><<<gAgg, 256>>>(b2);

    // ===== projection head =====
    sgemm_pipe<0><<<gemmGridP, 256>>>(p_z2, Wp, bp, out, NN, OUTD, DHEAD, nullptr, nullptr);
}

// round 5
// speedup vs baseline: 3.5374x; 1.2611x over previous
#include <cuda_runtime.h>
#include <cuda_fp16.h>
#include <math.h>
#include <stdint.h>

#define NN 50000
#define NE 800000
#define DHID 128
#define NH 4
#define DHEAD 32
#define OUTD 512
#define NEG_SLOPE 0.2f
#define EPSV 1e-9f

// ---------------- scratch (device globals; no allocation) ----------------
__device__ __half g_Whh[NN * DHID];   // fp16 message payload
__device__ float g_z[NN * DHID];
__device__ float g_el[NN * NH];
__device__ float g_er[NN * NH];
__device__ float g_z2[NN * DHEAD];
__device__ int   g_cnt[NN];
__device__ int   g_rowptr[NN + 1];
__device__ int   g_epos[NE];
__device__ int   g_csrc[NE];

__device__ __forceinline__ float lrelu(float x) {
    return x > 0.0f ? x : NEG_SLOPE * x;
}

__device__ __forceinline__ uint32_t f2tf32(float x) {
    uint32_t u;
    asm("cvt.rna.tf32.f32 %0, %1;" : "=r"(u) : "f"(x));
    return u;
}

__device__ __forceinline__ void mma_tf32(float* c, const uint32_t* a, const uint32_t* b) {
    asm volatile(
        "mma.sync.aligned.m16n8k8.row.col.f32.tf32.tf32.f32 "
        "{%0,%1,%2,%3}, {%4,%5,%6,%7}, {%8,%9}, {%0,%1,%2,%3};"
        : "+f"(c[0]), "+f"(c[1]), "+f"(c[2]), "+f"(c[3])
        : "r"(a[0]), "r"(a[1]), "r"(a[2]), "r"(a[3]), "r"(b[0]), "r"(b[1]));
}

// ---------------- streams/events for fork-join ----------------
static cudaStream_t g_s2;
static cudaEvent_t g_evFork, g_evCsr;
struct HostInit {
    HostInit() {
        cudaStreamCreateWithFlags(&g_s2, cudaStreamNonBlocking);
        cudaEventCreateWithFlags(&g_evFork, cudaEventDisableTiming);
        cudaEventCreateWithFlags(&g_evCsr, cudaEventDisableTiming);
    }
};
static HostInit g_hostInit;

// ================= CSR build =================
__global__ void k_count(const int* __restrict__ dst) {
    int e = blockIdx.x * blockDim.x + threadIdx.x;
    if (e < NE) g_epos[e] = atomicAdd(&g_cnt[dst[e]], 1);
}

__global__ void k_scan() {
    __shared__ int warpsum[32];
    const int T = 1024;
    const int CH = (NN + T - 1) / T;
    int t = threadIdx.x;
    int lane = t & 31, wid = t >> 5;
    int lo = t * CH;
    int hi = lo + CH; if (hi > NN) hi = NN;
    if (lo > NN) lo = NN;
    int s = 0;
    for (int i = lo; i < hi; i++) s += g_cnt[i];
    int v = s;
#pragma unroll
    for (int o = 1; o < 32; o <<= 1) {
        int u = __shfl_up_sync(0xFFFFFFFFu, v, o);
        if (lane >= o) v += u;
    }
    if (lane == 31) warpsum[wid] = v;
    __syncthreads();
    if (wid == 0) {
        int w = warpsum[lane];
#pragma unroll
        for (int o = 1; o < 32; o <<= 1) {
            int u = __shfl_up_sync(0xFFFFFFFFu, w, o);
            if (lane >= o) w += u;
        }
        warpsum[lane] = w;
    }
    __syncthreads();
    int excl = v - s + (wid > 0 ? warpsum[wid - 1] : 0);
    int run = excl;
    for (int i = lo; i < hi; i++) {
        g_rowptr[i] = run;
        run += g_cnt[i];
    }
    if (t == T - 1) g_rowptr[NN] = run;
}

__global__ void k_fill(const int* __restrict__ src, const int* __restrict__ dst) {
    int e = blockIdx.x * blockDim.x + threadIdx.x;
    if (e >= NE) return;
    int t = dst[e];
    g_csrc[g_rowptr[t] + g_epos[e]] = src[e];
}

// ================= tensor-core GEMM (tf32 mma.sync), 128x128 tile =================
// FUSE=1: writes fp16 g_Whh + g_el/g_er (grid.x must be 1, N==128); no fp32 C.
// FUSE=0: writes fp32 C (+bias).
// Requires K % 16 == 0, N % 128 == 0.
template <int FUSE>
__global__ void __launch_bounds__(256, 2)
gemm_tc(const float* __restrict__ A, const float* __restrict__ B,
        const float* __restrict__ bias, float* __restrict__ C,
        int M, int N, int K,
        const float* __restrict__ al, const float* __restrict__ ar) {
    __shared__ uint32_t As[2][128][20];   // [buf][m][k] tf32, padded
    __shared__ uint32_t Bs[2][16][132];   // [buf][k][n] tf32, padded

    const int tid = threadIdx.x;
    const int wid = tid >> 5, lane = tid & 31;
    const int g = lane >> 2, t = lane & 3;
    const int wm = wid & 3;               // 4 warp rows x 32
    const int wn = wid >> 2;              // 2 warp cols x 64
    const int rowBase = blockIdx.y * 128;
    const int colBase = blockIdx.x * 128;

    float acc[2][8][4];
#pragma unroll
    for (int mf = 0; mf < 2; mf++)
#pragma unroll
        for (int nf = 0; nf < 8; nf++)
#pragma unroll
            for (int r = 0; r < 4; r++) acc[mf][nf][r] = 0.0f;

    // ---- stage 0 load ----
    {
#pragma unroll
        for (int i = 0; i < 2; i++) {
            int slot = tid + i * 256;           // A: 512 float4 slots
            int row = slot >> 2, c4 = (slot & 3) * 4;
            float4 a4 = make_float4(0.f, 0.f, 0.f, 0.f);
            int gr = rowBase + row;
            if (gr < M) a4 = *(const float4*)(A + (size_t)gr * K + c4);
            As[0][row][c4 + 0] = f2tf32(a4.x);
            As[0][row][c4 + 1] = f2tf32(a4.y);
            As[0][row][c4 + 2] = f2tf32(a4.z);
            As[0][row][c4 + 3] = f2tf32(a4.w);
        }
#pragma unroll
        for (int i = 0; i < 2; i++) {
            int slot = tid + i * 256;           // B: 512 float4 slots
            int k = slot >> 5, n4 = (slot & 31) * 4;
            float4 b4 = *(const float4*)(B + (size_t)k * N + colBase + n4);
            Bs[0][k][n4 + 0] = f2tf32(b4.x);
            Bs[0][k][n4 + 1] = f2tf32(b4.y);
            Bs[0][k][n4 + 2] = f2tf32(b4.z);
            Bs[0][k][n4 + 3] = f2tf32(b4.w);
        }
    }
    __syncthreads();

    const int nStages = K >> 4;
    int cur = 0;
    for (int st = 0; st < nStages; st++) {
        float4 pa[2], pb[2];
        const bool hn = (st + 1) < nStages;
        if (hn) {
            int k0g = (st + 1) * 16;
#pragma unroll
            for (int i = 0; i < 2; i++) {
                int slot = tid + i * 256;
                int row = slot >> 2, c4 = (slot & 3) * 4;
                pa[i] = make_float4(0.f, 0.f, 0.f, 0.f);
                int gr = rowBase + row;
                if (gr < M) pa[i] = *(const float4*)(A + (size_t)gr * K + k0g + c4);
            }
#pragma unroll
            for (int i = 0; i < 2; i++) {
                int slot = tid + i * 256;
                int k = slot >> 5, n4 = (slot & 31) * 4;
                pb[i] = *(const float4*)(B + (size_t)(k0g + k) * N + colBase + n4);
            }
        }

#pragma unroll
        for (int kk = 0; kk < 2; kk++) {
            const int k0 = kk * 8;
            uint32_t af[2][4], bf[8][2];
#pragma unroll
            for (int mf = 0; mf < 2; mf++) {
                int r0 = wm * 32 + mf * 16 + g;
                af[mf][0] = As[cur][r0][k0 + t];
                af[mf][1] = As[cur][r0 + 8][k0 + t];
                af[mf][2] = As[cur][r0][k0 + t + 4];
                af[mf][3] = As[cur][r0 + 8][k0 + t + 4];
            }
#pragma unroll
            for (int nf = 0; nf < 8; nf++) {
                int n0 = wn * 64 + nf * 8 + g;
                bf[nf][0] = Bs[cur][k0 + t][n0];
                bf[nf][1] = Bs[cur][k0 + t + 4][n0];
            }
#pragma unroll
            for (int mf = 0; mf < 2; mf++)
#pragma unroll
                for (int nf = 0; nf < 8; nf++)
                    mma_tf32(acc[mf][nf], af[mf], bf[nf]);
        }

        if (hn) {
            int nb = cur ^ 1;
#pragma unroll
            for (int i = 0; i < 2; i++) {
                int slot = tid + i * 256;
                int row = slot >> 2, c4 = (slot & 3) * 4;
                As[nb][row][c4 + 0] = f2tf32(pa[i].x);
                As[nb][row][c4 + 1] = f2tf32(pa[i].y);
                As[nb][row][c4 + 2] = f2tf32(pa[i].z);
                As[nb][row][c4 + 3] = f2tf32(pa[i].w);
            }
#pragma unroll
            for (int i = 0; i < 2; i++) {
                int slot = tid + i * 256;
                int k = slot >> 5, n4 = (slot & 31) * 4;
                Bs[nb][k][n4 + 0] = f2tf32(pb[i].x);
                Bs[nb][k][n4 + 1] = f2tf32(pb[i].y);
                Bs[nb][k][n4 + 2] = f2tf32(pb[i].z);
                Bs[nb][k][n4 + 3] = f2tf32(pb[i].w);
            }
        }
        __syncthreads();
        cur ^= 1;
    }

    if (!FUSE) {
        // fp32 store (+bias)
#pragma unroll
        for (int mf = 0; mf < 2; mf++) {
            int row0 = rowBase + wm * 32 + mf * 16 + g;
#pragma unroll
            for (int nf = 0; nf < 8; nf++) {
                int col = colBase + wn * 64 + nf * 8 + 2 * t;
                float b0 = bias ? bias[col] : 0.f;
                float b1 = bias ? bias[col + 1] : 0.f;
                if (row0 < M) {
                    float2 v = make_float2(acc[mf][nf][0] + b0, acc[mf][nf][1] + b1);
                    *(float2*)(C + (size_t)row0 * N + col) = v;
                }
                if (row0 + 8 < M) {
                    float2 v = make_float2(acc[mf][nf][2] + b0, acc[mf][nf][3] + b1);
                    *(float2*)(C + (size_t)(row0 + 8) * N + col) = v;
                }
            }
        }
    } else {
        // fp16 payload + el/er epilogue (colBase==0, N==128)
        float elp[2][2][2] = {}, erp[2][2][2] = {};
#pragma unroll
        for (int nf = 0; nf < 8; nf++) {
            int hh = nf >> 2;
            int col = wn * 64 + nf * 8 + 2 * t;
            float la0 = al[col], la1 = al[col + 1];
            float ra0 = ar[col], ra1 = ar[col + 1];
#pragma unroll
            for (int mf = 0; mf < 2; mf++) {
                elp[mf][0][hh] += acc[mf][nf][0] * la0 + acc[mf][nf][1] * la1;
                elp[mf][1][hh] += acc[mf][nf][2] * la0 + acc[mf][nf][3] * la1;
                erp[mf][0][hh] += acc[mf][nf][0] * ra0 + acc[mf][nf][1] * ra1;
                erp[mf][1][hh] += acc[mf][nf][2] * ra0 + acc[mf][nf][3] * ra1;
                int row0 = rowBase + wm * 32 + mf * 16 + g;
                if (row0 < M) {
                    __half2 hv = __floats2half2_rn(acc[mf][nf][0], acc[mf][nf][1]);
                    *(__half2*)(g_Whh + (size_t)row0 * DHID + col) = hv;
                }
                if (row0 + 8 < M) {
                    __half2 hv = __floats2half2_rn(acc[mf][nf][2], acc[mf][nf][3]);
                    *(__half2*)(g_Whh + (size_t)(row0 + 8) * DHID + col) = hv;
                }
            }
        }
        // reduce over the 4 tig lanes in each group
#pragma unroll
        for (int mf = 0; mf < 2; mf++)
#pragma unroll
            for (int rh = 0; rh < 2; rh++)
#pragma unroll
                for (int hh = 0; hh < 2; hh++) {
                    float v = elp[mf][rh][hh];
                    v += __shfl_xor_sync(0xFFFFFFFFu, v, 1);
                    v += __shfl_xor_sync(0xFFFFFFFFu, v, 2);
                    elp[mf][rh][hh] = v;
                    float w = erp[mf][rh][hh];
                    w += __shfl_xor_sync(0xFFFFFFFFu, w, 1);
                    w += __shfl_xor_sync(0xFFFFFFFFu, w, 2);
                    erp[mf][rh][hh] = w;
                }
        float* el_s = (float*)&As[0][0][0];     // 128*5 floats
        float* er_s = el_s + 128 * 5;
        if (t == 0) {
#pragma unroll
            for (int mf = 0; mf < 2; mf++)
#pragma unroll
                for (int rh = 0; rh < 2; rh++) {
                    int rl = wm * 32 + mf * 16 + g + rh * 8;
#pragma unroll
                    for (int hh = 0; hh < 2; hh++) {
                        el_s[rl * 5 + wn * 2 + hh] = elp[mf][rh][hh];
                        er_s[rl * 5 + wn * 2 + hh] = erp[mf][rh][hh];
                    }
                }
        }
        __syncthreads();
        for (int p = tid; p < 512; p += 256) {
            int row = p >> 2, hh = p & 3;
            int gr = rowBase + row;
            if (gr < M) {
                g_el[gr * NH + hh] = el_s[row * 5 + hh];
                g_er[gr * NH + hh] = er_s[row * 5 + hh];
            }
        }
    }
}

// ================= fused softmax + aggregate (warp per node) ====
template <int LAYER>
__global__ void k_gat_agg(const float* __restrict__ bias) {
    int n = (blockIdx.x << 3) + (threadIdx.x >> 5);
    if (n >= NN) return;
    int lane = threadIdx.x & 31;
    int myh = lane >> 3;
    int beg = g_rowptr[n], end = g_rowptr[n + 1];
    float4 er4 = *(const float4*)(g_er + n * NH);

    float ax = 0.f, ay = 0.f, az = 0.f, aw = 0.f;
    float se0 = 0.f, se1 = 0.f, se2 = 0.f, se3 = 0.f;
    const __half* WhBase = g_Whh + (size_t)(lane * 4);

    for (int base = beg; base < end; base += 32) {
        int cnt = end - base; if (cnt > 32) cnt = 32;
        int sv = 0;
        float4 elv = make_float4(0.f, 0.f, 0.f, 0.f);
        if (lane < cnt) {
            sv = g_csrc[base + lane];
            elv = *(const float4*)(g_el + sv * NH);
        }
        float e0 = __expf(lrelu(elv.x + er4.x));
        float e1 = __expf(lrelu(elv.y + er4.y));
        float e2 = __expf(lrelu(elv.z + er4.z));
        float e3 = __expf(lrelu(elv.w + er4.w));
        if (lane >= cnt) { e0 = e1 = e2 = e3 = 0.f; }
        se0 += e0; se1 += e1; se2 += e2; se3 += e3;
#pragma unroll 4
        for (int j = 0; j < cnt; j++) {
            int s    = __shfl_sync(0xFFFFFFFFu, sv, j);
            float q0 = __shfl_sync(0xFFFFFFFFu, e0, j);
            float q1 = __shfl_sync(0xFFFFFFFFu, e1, j);
            float q2 = __shfl_sync(0xFFFFFFFFu, e2, j);
            float q3 = __shfl_sync(0xFFFFFFFFu, e3, j);
            float exh = myh < 2 ? (myh == 0 ? q0 : q1) : (myh == 2 ? q2 : q3);
            uint2 u = *(const uint2*)(WhBase + (size_t)s * DHID);
            float2 f0 = __half22float2(*(__half2*)&u.x);
            float2 f1 = __half22float2(*(__half2*)&u.y);
            ax = fmaf(exh, f0.x, ax);
            ay = fmaf(exh, f0.y, ay);
            az = fmaf(exh, f1.x, az);
            aw = fmaf(exh, f1.y, aw);
        }
    }
#pragma unroll
    for (int o = 16; o > 0; o >>= 1) {
        se0 += __shfl_xor_sync(0xFFFFFFFFu, se0, o);
        se1 += __shfl_xor_sync(0xFFFFFFFFu, se1, o);
        se2 += __shfl_xor_sync(0xFFFFFFFFu, se2, o);
        se3 += __shfl_xor_sync(0xFFFFFFFFu, se3, o);
    }
    float seh = myh < 2 ? (myh == 0 ? se0 : se1) : (myh == 2 ? se2 : se3);
    float r = 1.0f / (seh + EPSV);
    ax *= r; ay *= r; az *= r; aw *= r;

    if (LAYER == 1) {
        int d = lane * 4;
        float4 v;
        v.x = ax + bias[d + 0];
        v.y = ay + bias[d + 1];
        v.z = az + bias[d + 2];
        v.w = aw + bias[d + 3];
        v.x = v.x > 0.f ? v.x : (__expf(v.x) - 1.0f);
        v.y = v.y > 0.f ? v.y : (__expf(v.y) - 1.0f);
        v.z = v.z > 0.f ? v.z : (__expf(v.z) - 1.0f);
        v.w = v.w > 0.f ? v.w : (__expf(v.w) - 1.0f);
        *(float4*)(g_z + (size_t)n * DHID + d) = v;
    } else {
        int d = lane * 4;
        ax += bias[d + 0]; ay += bias[d + 1]; az += bias[d + 2]; aw += bias[d + 3];
#pragma unroll
        for (int o = 8; o <= 16; o <<= 1) {
            ax += __shfl_xor_sync(0xFFFFFFFFu, ax, o);
            ay += __shfl_xor_sync(0xFFFFFFFFu, ay, o);
            az += __shfl_xor_sync(0xFFFFFFFFu, az, o);
            aw += __shfl_xor_sync(0xFFFFFFFFu, aw, o);
        }
        if (lane < 8) {
            float4 v = make_float4(0.25f * ax, 0.25f * ay, 0.25f * az, 0.25f * aw);
            *(float4*)(g_z2 + (size_t)n * DHEAD + lane * 4) = v;
        }
    }
}

// ================= launch =================
extern "C" void kernel_launch(void* const* d_in, const int* in_sizes, int n_in,
                              void* d_out, int out_size) {
    const float* h   = (const float*)d_in[0];
    const int*   src = (const int*)d_in[1];
    const int*   dst = (const int*)d_in[2];
    const float* W1  = (const float*)d_in[3];
    const float* al1 = (const float*)d_in[4];
    const float* ar1 = (const float*)d_in[5];
    const float* b1  = (const float*)d_in[6];
    const float* W2  = (const float*)d_in[7];
    const float* al2 = (const float*)d_in[8];
    const float* ar2 = (const float*)d_in[9];
    const float* b2  = (const float*)d_in[10];
    const float* Wp  = (const float*)d_in[11];
    const float* bp  = (const float*)d_in[12];
    float* out = (float*)d_out;

    float *p_z, *p_z2;
    int *p_cnt;
    cudaGetSymbolAddress((void**)&p_z,   g_z);
    cudaGetSymbolAddress((void**)&p_z2,  g_z2);
    cudaGetSymbolAddress((void**)&p_cnt, g_cnt);

    const int TPB = 256;
    int gEdge = (NE + TPB - 1) / TPB;
    int gAgg  = (NN + 7) / 8;

    dim3 gemmGrid1(1, (NN + 127) / 128);            // N=128
    dim3 gemmGridP(OUTD / 128, (NN + 127) / 128);   // N=512

    // ---- fork: CSR build on side stream, GEMM1 on main stream ----
    cudaEventRecord(g_evFork, 0);
    cudaStreamWaitEvent(g_s2, g_evFork, 0);
    cudaMemsetAsync(p_cnt, 0, NN * sizeof(int), g_s2);
    k_count<<<gEdge, TPB, 0, g_s2>>>(dst);
    k_scan<<<1, 1024, 0, g_s2>>>();
    k_fill<<<gEdge, TPB, 0, g_s2>>>(src, dst);
    cudaEventRecord(g_evCsr, g_s2);

    // ===== layer 1 =====
    gemm_tc<1><<<gemmGrid1, 256>>>(h, W1, nullptr, nullptr, NN, DHID, DHID, al1, ar1);
    cudaStreamWaitEvent(0, g_evCsr, 0);   // join: agg needs CSR
    k_gat_agg<1><<<gAgg, 256>>>(b1);

    // ===== layer 2 =====
    gemm_tc<1><<<gemmGrid1, 256>>>(p_z, W2, nullptr, nullptr, NN, DHID, DHID, al2, ar2);
    k_gat_agg<2><<<gAgg, 256>>>(b2);

    // ===== projection head =====
    gemm_tc<0><<<gemmGridP, 256>>>(p_z2, Wp, bp, out, NN, OUTD, DHEAD, nullptr, nullptr);
}

// round 6
// speedup vs baseline: 3.6276x; 1.0255x over previous
#include <cuda_runtime.h>
#include <cuda_fp16.h>
#include <math.h>
#include <stdint.h>

#define NN 50000
#define NE 800000
#define DHID 128
#define NH 4
#define DHEAD 32
#define OUTD 512
#define NEG_SLOPE 0.2f
#define EPSV 1e-9f

// GEMM smem layout (floats): 3 stages A[128][20] + 3 stages B[16][132]
#define A_STRIDE 20
#define B_STRIDE 132
#define A_STAGE (128 * A_STRIDE)          // 2560
#define B_STAGE (16 * B_STRIDE)           // 2112
#define SMEM_FLOATS (3 * A_STAGE + 3 * B_STAGE)
#define SMEM_BYTES (SMEM_FLOATS * 4)      // 56064

// ---------------- scratch (device globals; no allocation) ----------------
__device__ __half g_Whh[NN * DHID];   // fp16 message payload
__device__ float g_z[NN * DHID];
__device__ float g_el[NN * NH];
__device__ float g_er[NN * NH];
__device__ float g_z2[NN * DHEAD];
__device__ int   g_cnt[NN];
__device__ int   g_rowptr[NN + 1];
__device__ int   g_epos[NE];
__device__ int   g_csrc[NE];

__device__ __forceinline__ float lrelu(float x) {
    return x > 0.0f ? x : NEG_SLOPE * x;
}

__device__ __forceinline__ uint32_t f2tf32(float x) {
    uint32_t u;
    asm("cvt.rna.tf32.f32 %0, %1;" : "=r"(u) : "f"(x));
    return u;
}

__device__ __forceinline__ void mma_tf32(float* c, const uint32_t* a, const uint32_t* b) {
    asm volatile(
        "mma.sync.aligned.m16n8k8.row.col.f32.tf32.tf32.f32 "
        "{%0,%1,%2,%3}, {%4,%5,%6,%7}, {%8,%9}, {%0,%1,%2,%3};"
        : "+f"(c[0]), "+f"(c[1]), "+f"(c[2]), "+f"(c[3])
        : "r"(a[0]), "r"(a[1]), "r"(a[2]), "r"(a[3]), "r"(b[0]), "r"(b[1]));
}

__device__ __forceinline__ uint32_t su(const void* p) {
    return (uint32_t)__cvta_generic_to_shared(p);
}

__device__ __forceinline__ void cp16(uint32_t dst, const void* src, bool p) {
    int sz = p ? 16 : 0;
    asm volatile("cp.async.cg.shared.global [%0], [%1], 16, %2;"
                 :: "r"(dst), "l"(src), "r"(sz));
}

// ================= tensor-core GEMM (tf32 mma.sync), 128x128 tile, cp.async x3 =====
// FUSE=1: writes fp16 g_Whh + g_el/g_er (grid.x must be 1, N==128); no fp32 C.
// FUSE=0: writes fp32 C (+bias).  Requires K % 16 == 0, K >= 32, N % 128 == 0.
template <int FUSE>
__global__ void __launch_bounds__(256, 2)
gemm_tc(const float* __restrict__ A, const float* __restrict__ B,
        const float* __restrict__ bias, float* __restrict__ C,
        int M, int N, int K,
        const float* __restrict__ al, const float* __restrict__ ar) {
    extern __shared__ float smem[];

    const int tid = threadIdx.x;
    const int wid = tid >> 5, lane = tid & 31;
    const int g = lane >> 2, t = lane & 3;
    const int wm = wid & 3;               // 4 warp rows x 32
    const int wn = wid >> 2;              // 2 warp cols x 64
    const int rowBase = blockIdx.y * 128;
    const int colBase = blockIdx.x * 128;

    // cp.async chunk coords (2 A-chunks + 2 B-chunks per thread per stage)
    const int aRow0 = tid >> 2, aK0 = (tid & 3) * 4;   // + chunk at aRow0+64
    const int bK0 = tid >> 5, bN0 = (tid & 31) * 4;    // + chunk at bK0+8
    const bool ap0 = (rowBase + aRow0) < M;
    const bool ap1 = (rowBase + aRow0 + 64) < M;
    const float* aSrc0 = A + (size_t)(ap0 ? rowBase + aRow0 : 0) * K + aK0;
    const float* aSrc1 = A + (size_t)(ap1 ? rowBase + aRow0 + 64 : 0) * K + aK0;
    const float* bSrc0 = B + (size_t)bK0 * N + colBase + bN0;
    const float* bSrc1 = B + (size_t)(bK0 + 8) * N + colBase + bN0;

    float acc[2][8][4];
#pragma unroll
    for (int mf = 0; mf < 2; mf++)
#pragma unroll
        for (int nf = 0; nf < 8; nf++)
#pragma unroll
            for (int r = 0; r < 4; r++) acc[mf][nf][r] = 0.0f;

    const int nStages = K >> 4;

    // smem dst addresses (per stage s add s*A_STAGE / s*B_STAGE floats)
    uint32_t aDst0 = su(smem + aRow0 * A_STRIDE + aK0);
    uint32_t aDst1 = su(smem + (aRow0 + 64) * A_STRIDE + aK0);
    uint32_t bDst0 = su(smem + 3 * A_STAGE + bK0 * B_STRIDE + bN0);
    uint32_t bDst1 = su(smem + 3 * A_STAGE + (bK0 + 8) * B_STRIDE + bN0);

    // prologue: stages 0 and 1
#pragma unroll
    for (int s = 0; s < 2; s++) {
        int k0g = s * 16;
        cp16(aDst0 + s * A_STAGE * 4, aSrc0 + k0g, ap0);
        cp16(aDst1 + s * A_STAGE * 4, aSrc1 + k0g, ap1);
        cp16(bDst0 + s * B_STAGE * 4, bSrc0 + (size_t)k0g * N, true);
        cp16(bDst1 + s * B_STAGE * 4, bSrc1 + (size_t)k0g * N, true);
        asm volatile("cp.async.commit_group;");
    }

    for (int st = 0; st < nStages; st++) {
        if (nStages - st >= 2) asm volatile("cp.async.wait_group 1;" ::: "memory");
        else                   asm volatile("cp.async.wait_group 0;" ::: "memory");
        __syncthreads();

        const int cur = st % 3;
        const float* Asf = smem + cur * A_STAGE;
        const float* Bsf = smem + 3 * A_STAGE + cur * B_STAGE;

#pragma unroll
        for (int kk = 0; kk < 2; kk++) {
            const int k0 = kk * 8;
            uint32_t af[2][4], bf[8][2];
#pragma unroll
            for (int mf = 0; mf < 2; mf++) {
                int r0 = wm * 32 + mf * 16 + g;
                af[mf][0] = f2tf32(Asf[r0 * A_STRIDE + k0 + t]);
                af[mf][1] = f2tf32(Asf[(r0 + 8) * A_STRIDE + k0 + t]);
                af[mf][2] = f2tf32(Asf[r0 * A_STRIDE + k0 + t + 4]);
                af[mf][3] = f2tf32(Asf[(r0 + 8) * A_STRIDE + k0 + t + 4]);
            }
#pragma unroll
            for (int nf = 0; nf < 8; nf++) {
                int n0 = wn * 64 + nf * 8 + g;
                bf[nf][0] = f2tf32(Bsf[(k0 + t) * B_STRIDE + n0]);
                bf[nf][1] = f2tf32(Bsf[(k0 + t + 4) * B_STRIDE + n0]);
            }
#pragma unroll
            for (int mf = 0; mf < 2; mf++)
#pragma unroll
                for (int nf = 0; nf < 8; nf++)
                    mma_tf32(acc[mf][nf], af[mf], bf[nf]);
        }

        if (st + 2 < nStages) {
            int s = (st + 2) % 3;
            int k0g = (st + 2) * 16;
            cp16(aDst0 + s * A_STAGE * 4, aSrc0 + k0g, ap0);
            cp16(aDst1 + s * A_STAGE * 4, aSrc1 + k0g, ap1);
            cp16(bDst0 + s * B_STAGE * 4, bSrc0 + (size_t)k0g * N, true);
            cp16(bDst1 + s * B_STAGE * 4, bSrc1 + (size_t)k0g * N, true);
            asm volatile("cp.async.commit_group;");
        }
    }
    __syncthreads();

    if (!FUSE) {
#pragma unroll
        for (int mf = 0; mf < 2; mf++) {
            int row0 = rowBase + wm * 32 + mf * 16 + g;
#pragma unroll
            for (int nf = 0; nf < 8; nf++) {
                int col = colBase + wn * 64 + nf * 8 + 2 * t;
                float b0 = bias ? bias[col] : 0.f;
                float b1 = bias ? bias[col + 1] : 0.f;
                if (row0 < M) {
                    float2 v = make_float2(acc[mf][nf][0] + b0, acc[mf][nf][1] + b1);
                    *(float2*)(C + (size_t)row0 * N + col) = v;
                }
                if (row0 + 8 < M) {
                    float2 v = make_float2(acc[mf][nf][2] + b0, acc[mf][nf][3] + b1);
                    *(float2*)(C + (size_t)(row0 + 8) * N + col) = v;
                }
            }
        }
    } else {
        // fp16 payload + el/er epilogue (colBase==0, N==128)
        float elp[2][2][2] = {}, erp[2][2][2] = {};
#pragma unroll
        for (int nf = 0; nf < 8; nf++) {
            int hh = nf >> 2;
            int col = wn * 64 + nf * 8 + 2 * t;
            float la0 = al[col], la1 = al[col + 1];
            float ra0 = ar[col], ra1 = ar[col + 1];
#pragma unroll
            for (int mf = 0; mf < 2; mf++) {
                elp[mf][0][hh] += acc[mf][nf][0] * la0 + acc[mf][nf][1] * la1;
                elp[mf][1][hh] += acc[mf][nf][2] * la0 + acc[mf][nf][3] * la1;
                erp[mf][0][hh] += acc[mf][nf][0] * ra0 + acc[mf][nf][1] * ra1;
                erp[mf][1][hh] += acc[mf][nf][2] * ra0 + acc[mf][nf][3] * ra1;
                int row0 = rowBase + wm * 32 + mf * 16 + g;
                if (row0 < M) {
                    __half2 hv = __floats2half2_rn(acc[mf][nf][0], acc[mf][nf][1]);
                    *(__half2*)(g_Whh + (size_t)row0 * DHID + col) = hv;
                }
                if (row0 + 8 < M) {
                    __half2 hv = __floats2half2_rn(acc[mf][nf][2], acc[mf][nf][3]);
                    *(__half2*)(g_Whh + (size_t)(row0 + 8) * DHID + col) = hv;
                }
            }
        }
#pragma unroll
        for (int mf = 0; mf < 2; mf++)
#pragma unroll
            for (int rh = 0; rh < 2; rh++)
#pragma unroll
                for (int hh = 0; hh < 2; hh++) {
                    float v = elp[mf][rh][hh];
                    v += __shfl_xor_sync(0xFFFFFFFFu, v, 1);
                    v += __shfl_xor_sync(0xFFFFFFFFu, v, 2);
                    elp[mf][rh][hh] = v;
                    float w = erp[mf][rh][hh];
                    w += __shfl_xor_sync(0xFFFFFFFFu, w, 1);
                    w += __shfl_xor_sync(0xFFFFFFFFu, w, 2);
                    erp[mf][rh][hh] = w;
                }
        float* el_s = smem;              // 640 floats
        float* er_s = smem + 640;
        if (t == 0) {
#pragma unroll
            for (int mf = 0; mf < 2; mf++)
#pragma unroll
                for (int rh = 0; rh < 2; rh++) {
                    int rl = wm * 32 + mf * 16 + g + rh * 8;
#pragma unroll
                    for (int hh = 0; hh < 2; hh++) {
                        el_s[rl * 5 + wn * 2 + hh] = elp[mf][rh][hh];
                        er_s[rl * 5 + wn * 2 + hh] = erp[mf][rh][hh];
                    }
                }
        }
        __syncthreads();
        for (int p = tid; p < 512; p += 256) {
            int row = p >> 2, hh = p & 3;
            int gr = rowBase + row;
            if (gr < M) {
                g_el[gr * NH + hh] = el_s[row * 5 + hh];
                g_er[gr * NH + hh] = er_s[row * 5 + hh];
            }
        }
    }
}

// ---------------- streams/events for fork-join + func attrs ----------------
static cudaStream_t g_s2;
static cudaEvent_t g_evFork, g_evCsr;
struct HostInit {
    HostInit() {
        cudaStreamCreateWithFlags(&g_s2, cudaStreamNonBlocking);
        cudaEventCreateWithFlags(&g_evFork, cudaEventDisableTiming);
        cudaEventCreateWithFlags(&g_evCsr, cudaEventDisableTiming);
        cudaFuncSetAttribute(gemm_tc<0>, cudaFuncAttributeMaxDynamicSharedMemorySize, SMEM_BYTES);
        cudaFuncSetAttribute(gemm_tc<1>, cudaFuncAttributeMaxDynamicSharedMemorySize, SMEM_BYTES);
    }
};
static HostInit g_hostInit;

// ================= CSR build (int4-vectorized) =================
__global__ void k_count(const int4* __restrict__ dst4) {
    int i = blockIdx.x * blockDim.x + threadIdx.x;
    if (i >= NE / 4) return;
    int4 d = dst4[i];
    int4 p;
    p.x = atomicAdd(&g_cnt[d.x], 1);
    p.y = atomicAdd(&g_cnt[d.y], 1);
    p.z = atomicAdd(&g_cnt[d.z], 1);
    p.w = atomicAdd(&g_cnt[d.w], 1);
    ((int4*)g_epos)[i] = p;
}

__global__ void k_scan() {
    __shared__ int warpsum[32];
    const int T = 1024;
    const int CH = (NN + T - 1) / T;
    int t = threadIdx.x;
    int lane = t & 31, wid = t >> 5;
    int lo = t * CH;
    int hi = lo + CH; if (hi > NN) hi = NN;
    if (lo > NN) lo = NN;
    int s = 0;
    for (int i = lo; i < hi; i++) s += g_cnt[i];
    int v = s;
#pragma unroll
    for (int o = 1; o < 32; o <<= 1) {
        int u = __shfl_up_sync(0xFFFFFFFFu, v, o);
        if (lane >= o) v += u;
    }
    if (lane == 31) warpsum[wid] = v;
    __syncthreads();
    if (wid == 0) {
        int w = warpsum[lane];
#pragma unroll
        for (int o = 1; o < 32; o <<= 1) {
            int u = __shfl_up_sync(0xFFFFFFFFu, w, o);
            if (lane >= o) w += u;
        }
        warpsum[lane] = w;
    }
    __syncthreads();
    int excl = v - s + (wid > 0 ? warpsum[wid - 1] : 0);
    int run = excl;
    for (int i = lo; i < hi; i++) {
        g_rowptr[i] = run;
        run += g_cnt[i];
    }
    if (t == T - 1) g_rowptr[NN] = run;
}

__global__ void k_fill(const int4* __restrict__ src4, const int4* __restrict__ dst4) {
    int i = blockIdx.x * blockDim.x + threadIdx.x;
    if (i >= NE / 4) return;
    int4 s = src4[i];
    int4 d = dst4[i];
    int4 p = ((const int4*)g_epos)[i];
    g_csrc[g_rowptr[d.x] + p.x] = s.x;
    g_csrc[g_rowptr[d.y] + p.y] = s.y;
    g_csrc[g_rowptr[d.z] + p.z] = s.z;
    g_csrc[g_rowptr[d.w] + p.w] = s.w;
}

// ================= fused softmax + aggregate (warp per node) ====
template <int LAYER>
__global__ void k_gat_agg(const float* __restrict__ bias) {
    int n = (blockIdx.x << 3) + (threadIdx.x >> 5);
    if (n >= NN) return;
    int lane = threadIdx.x & 31;
    int myh = lane >> 3;
    int beg = g_rowptr[n], end = g_rowptr[n + 1];
    float4 er4 = *(const float4*)(g_er + n * NH);

    float ax = 0.f, ay = 0.f, az = 0.f, aw = 0.f;
    float se0 = 0.f, se1 = 0.f, se2 = 0.f, se3 = 0.f;
    const __half* WhBase = g_Whh + (size_t)(lane * 4);

    for (int base = beg; base < end; base += 32) {
        int cnt = end - base; if (cnt > 32) cnt = 32;
        int sv = 0;
        float4 elv = make_float4(0.f, 0.f, 0.f, 0.f);
        if (lane < cnt) {
            sv = g_csrc[base + lane];
            elv = *(const float4*)(g_el + sv * NH);
        }
        float e0 = __expf(lrelu(elv.x + er4.x));
        float e1 = __expf(lrelu(elv.y + er4.y));
        float e2 = __expf(lrelu(elv.z + er4.z));
        float e3 = __expf(lrelu(elv.w + er4.w));
        if (lane >= cnt) { e0 = e1 = e2 = e3 = 0.f; }
        se0 += e0; se1 += e1; se2 += e2; se3 += e3;
#pragma unroll 8
        for (int j = 0; j < cnt; j++) {
            int s    = __shfl_sync(0xFFFFFFFFu, sv, j);
            float q0 = __shfl_sync(0xFFFFFFFFu, e0, j);
            float q1 = __shfl_sync(0xFFFFFFFFu, e1, j);
            float q2 = __shfl_sync(0xFFFFFFFFu, e2, j);
            float q3 = __shfl_sync(0xFFFFFFFFu, e3, j);
            float exh = myh < 2 ? (myh == 0 ? q0 : q1) : (myh == 2 ? q2 : q3);
            uint2 u = *(const uint2*)(WhBase + (size_t)s * DHID);
            float2 f0 = __half22float2(*(__half2*)&u.x);
            float2 f1 = __half22float2(*(__half2*)&u.y);
            ax = fmaf(exh, f0.x, ax);
            ay = fmaf(exh, f0.y, ay);
            az = fmaf(exh, f1.x, az);
            aw = fmaf(exh, f1.y, aw);
        }
    }
#pragma unroll
    for (int o = 16; o > 0; o >>= 1) {
        se0 += __shfl_xor_sync(0xFFFFFFFFu, se0, o);
        se1 += __shfl_xor_sync(0xFFFFFFFFu, se1, o);
        se2 += __shfl_xor_sync(0xFFFFFFFFu, se2, o);
        se3 += __shfl_xor_sync(0xFFFFFFFFu, se3, o);
    }
    float seh = myh < 2 ? (myh == 0 ? se0 : se1) : (myh == 2 ? se2 : se3);
    float r = 1.0f / (seh + EPSV);
    ax *= r; ay *= r; az *= r; aw *= r;

    if (LAYER == 1) {
        int d = lane * 4;
        float4 v;
        v.x = ax + bias[d + 0];
        v.y = ay + bias[d + 1];
        v.z = az + bias[d + 2];
        v.w = aw + bias[d + 3];
        v.x = v.x > 0.f ? v.x : (__expf(v.x) - 1.0f);
        v.y = v.y > 0.f ? v.y : (__expf(v.y) - 1.0f);
        v.z = v.z > 0.f ? v.z : (__expf(v.z) - 1.0f);
        v.w = v.w > 0.f ? v.w : (__expf(v.w) - 1.0f);
        *(float4*)(g_z + (size_t)n * DHID + d) = v;
    } else {
        int d = lane * 4;
        ax += bias[d + 0]; ay += bias[d + 1]; az += bias[d + 2]; aw += bias[d + 3];
#pragma unroll
        for (int o = 8; o <= 16; o <<= 1) {
            ax += __shfl_xor_sync(0xFFFFFFFFu, ax, o);
            ay += __shfl_xor_sync(0xFFFFFFFFu, ay, o);
            az += __shfl_xor_sync(0xFFFFFFFFu, az, o);
            aw += __shfl_xor_sync(0xFFFFFFFFu, aw, o);
        }
        if (lane < 8) {
            float4 v = make_float4(0.25f * ax, 0.25f * ay, 0.25f * az, 0.25f * aw);
            *(float4*)(g_z2 + (size_t)n * DHEAD + lane * 4) = v;
        }
    }
}

// ================= launch =================
extern "C" void kernel_launch(void* const* d_in, const int* in_sizes, int n_in,
                              void* d_out, int out_size) {
    const float* h   = (const float*)d_in[0];
    const int*   src = (const int*)d_in[1];
    const int*   dst = (const int*)d_in[2];
    const float* W1  = (const float*)d_in[3];
    const float* al1 = (const float*)d_in[4];
    const float* ar1 = (const float*)d_in[5];
    const float* b1  = (const float*)d_in[6];
    const float* W2  = (const float*)d_in[7];
    const float* al2 = (const float*)d_in[8];
    const float* ar2 = (const float*)d_in[9];
    const float* b2  = (const float*)d_in[10];
    const float* Wp  = (const float*)d_in[11];
    const float* bp  = (const float*)d_in[12];
    float* out = (float*)d_out;

    float *p_z, *p_z2;
    int *p_cnt;
    cudaGetSymbolAddress((void**)&p_z,   g_z);
    cudaGetSymbolAddress((void**)&p_z2,  g_z2);
    cudaGetSymbolAddress((void**)&p_cnt, g_cnt);

    const int TPB = 256;
    int gEdge4 = (NE / 4 + TPB - 1) / TPB;
    int gAgg   = (NN + 7) / 8;

    dim3 gemmGrid1(1, (NN + 127) / 128);            // N=128
    dim3 gemmGridP(OUTD / 128, (NN + 127) / 128);   // N=512

    // ---- fork: CSR build on side stream, GEMM1 on main stream ----
    cudaEventRecord(g_evFork, 0);
    cudaStreamWaitEvent(g_s2, g_evFork, 0);
    cudaMemsetAsync(p_cnt, 0, NN * sizeof(int), g_s2);
    k_count<<<gEdge4, TPB, 0, g_s2>>>((const int4*)dst);
    k_scan<<<1, 1024, 0, g_s2>>>();
    k_fill<<<gEdge4, TPB, 0, g_s2>>>((const int4*)src, (const int4*)dst);
    cudaEventRecord(g_evCsr, g_s2);

    // ===== layer 1 =====
    gemm_tc<1><<<gemmGrid1, 256, SMEM_BYTES>>>(h, W1, nullptr, nullptr, NN, DHID, DHID, al1, ar1);
    cudaStreamWaitEvent(0, g_evCsr, 0);   // join: agg needs CSR
    k_gat_agg<1><<<gAgg, 256>>>(b1);

    // ===== layer 2 =====
    gemm_tc<1><<<gemmGrid1, 256, SMEM_BYTES>>>(p_z, W2, nullptr, nullptr, NN, DHID, DHID, al2, ar2);
    k_gat_agg<2><<<gAgg, 256>>>(b2);

    // ===== projection head =====
    gemm_tc<0><<<gemmGridP, 256, SMEM_BYTES>>>(p_z2, Wp, bp, out, NN, OUTD, DHEAD, nullptr, nullptr);
}

// round 7
// speedup vs baseline: 3.8498x; 1.0613x over previous
#include <cuda_runtime.h>
#include <cuda_fp16.h>
#include <math.h>
#include <stdint.h>

#define NN 50000
#define NE 800000
#define DHID 128
#define NH 4
#define DHEAD 32
#define OUTD 512
#define NEG_SLOPE 0.2f
#define EPSV 1e-9f

// GEMM smem layout (floats): 3 stages A[64][20] + 3 stages B[16][132]
#define A_STRIDE 20
#define B_STRIDE 132
#define A_STAGE (64 * A_STRIDE)           // 1280
#define B_STAGE (16 * B_STRIDE)           // 2112
#define SMEM_FLOATS (3 * A_STAGE + 3 * B_STAGE)
#define SMEM_BYTES (SMEM_FLOATS * 4)      // 40704

// ---------------- scratch (device globals; no allocation) ----------------
__device__ __half g_Whh[NN * DHID];   // fp16 message payload
__device__ float g_z[NN * DHID];
__device__ float g_el[NN * NH];
__device__ float g_er[NN * NH];
__device__ float g_z2[NN * DHEAD];
__device__ int   g_cnt[NN];
__device__ int   g_rowptr[NN + 1];
__device__ int   g_epos[NE];
__device__ int   g_csrc[NE];

__device__ __forceinline__ float lrelu(float x) {
    return x > 0.0f ? x : NEG_SLOPE * x;
}

__device__ __forceinline__ uint32_t f2tf32(float x) {
    uint32_t u;
    asm("cvt.rna.tf32.f32 %0, %1;" : "=r"(u) : "f"(x));
    return u;
}

__device__ __forceinline__ void mma_tf32(float* c, const uint32_t* a, const uint32_t* b) {
    asm volatile(
        "mma.sync.aligned.m16n8k8.row.col.f32.tf32.tf32.f32 "
        "{%0,%1,%2,%3}, {%4,%5,%6,%7}, {%8,%9}, {%0,%1,%2,%3};"
        : "+f"(c[0]), "+f"(c[1]), "+f"(c[2]), "+f"(c[3])
        : "r"(a[0]), "r"(a[1]), "r"(a[2]), "r"(a[3]), "r"(b[0]), "r"(b[1]));
}

__device__ __forceinline__ uint32_t su(const void* p) {
    return (uint32_t)__cvta_generic_to_shared(p);
}

__device__ __forceinline__ void cp16(uint32_t dst, const void* src, bool p) {
    int sz = p ? 16 : 0;
    asm volatile("cp.async.cg.shared.global [%0], [%1], 16, %2;"
                 :: "r"(dst), "l"(src), "r"(sz));
}

// ================= tensor-core GEMM (tf32 mma.sync) =================
// Block tile 64x128, 8 warps (2m x 4n) of 32x32 warp tiles, 3-stage cp.async.
// FUSE=1: writes fp16 g_Whh + g_el/g_er (grid.x must be 1, N==128); no fp32 C.
// FUSE=0: writes fp32 C (+bias).  Requires K % 16 == 0, K >= 32, N % 128 == 0.
template <int FUSE>
__global__ void __launch_bounds__(256, 3)
gemm_tc(const float* __restrict__ A, const float* __restrict__ B,
        const float* __restrict__ bias, float* __restrict__ C,
        int M, int N, int K,
        const float* __restrict__ al, const float* __restrict__ ar) {
    extern __shared__ float smem[];

    const int tid = threadIdx.x;
    const int wid = tid >> 5, lane = tid & 31;
    const int g = lane >> 2, t = lane & 3;
    const int wm = wid & 1;               // 2 warp rows x 32
    const int wn = wid >> 1;              // 4 warp cols x 32
    const int rowBase = blockIdx.y * 64;
    const int colBase = blockIdx.x * 128;

    // cp.async coords: A 1 chunk/thread, B 2 chunks/thread
    const int aRow = tid >> 2, aK0 = (tid & 3) * 4;
    const int bK0 = tid >> 5, bN0 = (tid & 31) * 4;
    const bool ap = (rowBase + aRow) < M;
    const float* aSrc = A + (size_t)(ap ? rowBase + aRow : 0) * K + aK0;
    const float* bSrc0 = B + (size_t)bK0 * N + colBase + bN0;
    const float* bSrc1 = B + (size_t)(bK0 + 8) * N + colBase + bN0;

    float acc[2][4][4];
#pragma unroll
    for (int mf = 0; mf < 2; mf++)
#pragma unroll
        for (int nf = 0; nf < 4; nf++)
#pragma unroll
            for (int r = 0; r < 4; r++) acc[mf][nf][r] = 0.0f;

    const int nStages = K >> 4;

    uint32_t aDst = su(smem + aRow * A_STRIDE + aK0);
    uint32_t bDst0 = su(smem + 3 * A_STAGE + bK0 * B_STRIDE + bN0);
    uint32_t bDst1 = su(smem + 3 * A_STAGE + (bK0 + 8) * B_STRIDE + bN0);

    // prologue: stages 0 and 1
#pragma unroll
    for (int s = 0; s < 2; s++) {
        int k0g = s * 16;
        cp16(aDst + s * A_STAGE * 4, aSrc + k0g, ap);
        cp16(bDst0 + s * B_STAGE * 4, bSrc0 + (size_t)k0g * N, true);
        cp16(bDst1 + s * B_STAGE * 4, bSrc1 + (size_t)k0g * N, true);
        asm volatile("cp.async.commit_group;");
    }

    for (int st = 0; st < nStages; st++) {
        if (nStages - st >= 2) asm volatile("cp.async.wait_group 1;" ::: "memory");
        else                   asm volatile("cp.async.wait_group 0;" ::: "memory");
        __syncthreads();

        const int cur = st % 3;
        const float* Asf = smem + cur * A_STAGE;
        const float* Bsf = smem + 3 * A_STAGE + cur * B_STAGE;

#pragma unroll
        for (int kk = 0; kk < 2; kk++) {
            const int k0 = kk * 8;
            uint32_t af[2][4], bf[4][2];
#pragma unroll
            for (int mf = 0; mf < 2; mf++) {
                int r0 = wm * 32 + mf * 16 + g;
                af[mf][0] = f2tf32(Asf[r0 * A_STRIDE + k0 + t]);
                af[mf][1] = f2tf32(Asf[(r0 + 8) * A_STRIDE + k0 + t]);
                af[mf][2] = f2tf32(Asf[r0 * A_STRIDE + k0 + t + 4]);
                af[mf][3] = f2tf32(Asf[(r0 + 8) * A_STRIDE + k0 + t + 4]);
            }
#pragma unroll
            for (int nf = 0; nf < 4; nf++) {
                int n0 = wn * 32 + nf * 8 + g;
                bf[nf][0] = f2tf32(Bsf[(k0 + t) * B_STRIDE + n0]);
                bf[nf][1] = f2tf32(Bsf[(k0 + t + 4) * B_STRIDE + n0]);
            }
#pragma unroll
            for (int mf = 0; mf < 2; mf++)
#pragma unroll
                for (int nf = 0; nf < 4; nf++)
                    mma_tf32(acc[mf][nf], af[mf], bf[nf]);
        }

        if (st + 2 < nStages) {
            int s = (st + 2) % 3;
            int k0g = (st + 2) * 16;
            cp16(aDst + s * A_STAGE * 4, aSrc + k0g, ap);
            cp16(bDst0 + s * B_STAGE * 4, bSrc0 + (size_t)k0g * N, true);
            cp16(bDst1 + s * B_STAGE * 4, bSrc1 + (size_t)k0g * N, true);
            asm volatile("cp.async.commit_group;");
        }
    }

    if (!FUSE) {
#pragma unroll
        for (int mf = 0; mf < 2; mf++) {
            int row0 = rowBase + wm * 32 + mf * 16 + g;
#pragma unroll
            for (int nf = 0; nf < 4; nf++) {
                int col = colBase + wn * 32 + nf * 8 + 2 * t;
                float b0 = bias ? bias[col] : 0.f;
                float b1 = bias ? bias[col + 1] : 0.f;
                if (row0 < M) {
                    float2 v = make_float2(acc[mf][nf][0] + b0, acc[mf][nf][1] + b1);
                    *(float2*)(C + (size_t)row0 * N + col) = v;
                }
                if (row0 + 8 < M) {
                    float2 v = make_float2(acc[mf][nf][2] + b0, acc[mf][nf][3] + b1);
                    *(float2*)(C + (size_t)(row0 + 8) * N + col) = v;
                }
            }
        }
    } else {
        // Each warp owns head wn entirely (cols wn*32..wn*32+31).
        float elp[2][2] = {}, erp[2][2] = {};   // [mf][rh]
#pragma unroll
        for (int nf = 0; nf < 4; nf++) {
            int col = wn * 32 + nf * 8 + 2 * t;
            float la0 = al[col], la1 = al[col + 1];
            float ra0 = ar[col], ra1 = ar[col + 1];
#pragma unroll
            for (int mf = 0; mf < 2; mf++) {
                elp[mf][0] += acc[mf][nf][0] * la0 + acc[mf][nf][1] * la1;
                elp[mf][1] += acc[mf][nf][2] * la0 + acc[mf][nf][3] * la1;
                erp[mf][0] += acc[mf][nf][0] * ra0 + acc[mf][nf][1] * ra1;
                erp[mf][1] += acc[mf][nf][2] * ra0 + acc[mf][nf][3] * ra1;
                int row0 = rowBase + wm * 32 + mf * 16 + g;
                if (row0 < M) {
                    __half2 hv = __floats2half2_rn(acc[mf][nf][0], acc[mf][nf][1]);
                    *(__half2*)(g_Whh + (size_t)row0 * DHID + col) = hv;
                }
                if (row0 + 8 < M) {
                    __half2 hv = __floats2half2_rn(acc[mf][nf][2], acc[mf][nf][3]);
                    *(__half2*)(g_Whh + (size_t)(row0 + 8) * DHID + col) = hv;
                }
            }
        }
        // reduce over t (lanes with same g)
#pragma unroll
        for (int mf = 0; mf < 2; mf++)
#pragma unroll
            for (int rh = 0; rh < 2; rh++) {
                float v = elp[mf][rh];
                v += __shfl_xor_sync(0xFFFFFFFFu, v, 1);
                v += __shfl_xor_sync(0xFFFFFFFFu, v, 2);
                elp[mf][rh] = v;
                float w = erp[mf][rh];
                w += __shfl_xor_sync(0xFFFFFFFFu, w, 1);
                w += __shfl_xor_sync(0xFFFFFFFFu, w, 2);
                erp[mf][rh] = w;
            }
        if (t == 0) {
#pragma unroll
            for (int mf = 0; mf < 2; mf++)
#pragma unroll
                for (int rh = 0; rh < 2; rh++) {
                    int gr = rowBase + wm * 32 + mf * 16 + g + rh * 8;
                    if (gr < M) {
                        g_el[gr * NH + wn] = elp[mf][rh];
                        g_er[gr * NH + wn] = erp[mf][rh];
                    }
                }
        }
    }
}

// ---------------- streams/events for fork-join + func attrs ----------------
static cudaStream_t g_s2;
static cudaEvent_t g_evFork, g_evCsr;
struct HostInit {
    HostInit() {
        cudaStreamCreateWithFlags(&g_s2, cudaStreamNonBlocking);
        cudaEventCreateWithFlags(&g_evFork, cudaEventDisableTiming);
        cudaEventCreateWithFlags(&g_evCsr, cudaEventDisableTiming);
        cudaFuncSetAttribute(gemm_tc<0>, cudaFuncAttributeMaxDynamicSharedMemorySize, SMEM_BYTES);
        cudaFuncSetAttribute(gemm_tc<1>, cudaFuncAttributeMaxDynamicSharedMemorySize, SMEM_BYTES);
    }
};
static HostInit g_hostInit;

// ================= CSR build (int4-vectorized) =================
__global__ void k_count(const int4* __restrict__ dst4) {
    int i = blockIdx.x * blockDim.x + threadIdx.x;
    if (i >= NE / 4) return;
    int4 d = dst4[i];
    int4 p;
    p.x = atomicAdd(&g_cnt[d.x], 1);
    p.y = atomicAdd(&g_cnt[d.y], 1);
    p.z = atomicAdd(&g_cnt[d.z], 1);
    p.w = atomicAdd(&g_cnt[d.w], 1);
    ((int4*)g_epos)[i] = p;
}

__global__ void k_scan() {
    __shared__ int warpsum[32];
    const int T = 1024;
    const int CH = (NN + T - 1) / T;
    int t = threadIdx.x;
    int lane = t & 31, wid = t >> 5;
    int lo = t * CH;
    int hi = lo + CH; if (hi > NN) hi = NN;
    if (lo > NN) lo = NN;
    int s = 0;
    for (int i = lo; i < hi; i++) s += g_cnt[i];
    int v = s;
#pragma unroll
    for (int o = 1; o < 32; o <<= 1) {
        int u = __shfl_up_sync(0xFFFFFFFFu, v, o);
        if (lane >= o) v += u;
    }
    if (lane == 31) warpsum[wid] = v;
    __syncthreads();
    if (wid == 0) {
        int w = warpsum[lane];
#pragma unroll
        for (int o = 1; o < 32; o <<= 1) {
            int u = __shfl_up_sync(0xFFFFFFFFu, w, o);
            if (lane >= o) w += u;
        }
        warpsum[lane] = w;
    }
    __syncthreads();
    int excl = v - s + (wid > 0 ? warpsum[wid - 1] : 0);
    int run = excl;
    for (int i = lo; i < hi; i++) {
        g_rowptr[i] = run;
        run += g_cnt[i];
    }
    if (t == T - 1) g_rowptr[NN] = run;
}

__global__ void k_fill(const int4* __restrict__ src4, const int4* __restrict__ dst4) {
    int i = blockIdx.x * blockDim.x + threadIdx.x;
    if (i >= NE / 4) return;
    int4 s = src4[i];
    int4 d = dst4[i];
    int4 p = ((const int4*)g_epos)[i];
    g_csrc[g_rowptr[d.x] + p.x] = s.x;
    g_csrc[g_rowptr[d.y] + p.y] = s.y;
    g_csrc[g_rowptr[d.z] + p.z] = s.z;
    g_csrc[g_rowptr[d.w] + p.w] = s.w;
}

// ================= fused softmax + aggregate (warp per node, smem exp stage) ====
template <int LAYER>
__global__ void k_gat_agg(const float* __restrict__ bias) {
    __shared__ float exsAll[8][128];
    int wIn = threadIdx.x >> 5;
    int n = (blockIdx.x << 3) + wIn;
    if (n >= NN) return;
    float* exsw = exsAll[wIn];
    int lane = threadIdx.x & 31;
    int myh = lane >> 3;
    int beg = g_rowptr[n], end = g_rowptr[n + 1];
    float4 er4 = *(const float4*)(g_er + n * NH);

    float ax = 0.f, ay = 0.f, az = 0.f, aw = 0.f;
    float se0 = 0.f, se1 = 0.f, se2 = 0.f, se3 = 0.f;
    const __half* WhBase = g_Whh + (size_t)(lane * 4);

    for (int base = beg; base < end; base += 32) {
        int cnt = end - base; if (cnt > 32) cnt = 32;
        int sv = 0;
        float4 elv = make_float4(0.f, 0.f, 0.f, 0.f);
        if (lane < cnt) {
            sv = g_csrc[base + lane];
            elv = *(const float4*)(g_el + sv * NH);
        }
        float e0 = __expf(lrelu(elv.x + er4.x));
        float e1 = __expf(lrelu(elv.y + er4.y));
        float e2 = __expf(lrelu(elv.z + er4.z));
        float e3 = __expf(lrelu(elv.w + er4.w));
        if (lane >= cnt) { e0 = e1 = e2 = e3 = 0.f; }
        se0 += e0; se1 += e1; se2 += e2; se3 += e3;
        __syncwarp();
        *(float4*)&exsw[lane * 4] = make_float4(e0, e1, e2, e3);
        __syncwarp();
#pragma unroll 8
        for (int j = 0; j < cnt; j++) {
            int s = __shfl_sync(0xFFFFFFFFu, sv, j);
            float exh = exsw[j * 4 + myh];
            uint2 u = *(const uint2*)(WhBase + (size_t)s * DHID);
            float2 f0 = __half22float2(*(__half2*)&u.x);
            float2 f1 = __half22float2(*(__half2*)&u.y);
            ax = fmaf(exh, f0.x, ax);
            ay = fmaf(exh, f0.y, ay);
            az = fmaf(exh, f1.x, az);
            aw = fmaf(exh, f1.y, aw);
        }
    }
#pragma unroll
    for (int o = 16; o > 0; o >>= 1) {
        se0 += __shfl_xor_sync(0xFFFFFFFFu, se0, o);
        se1 += __shfl_xor_sync(0xFFFFFFFFu, se1, o);
        se2 += __shfl_xor_sync(0xFFFFFFFFu, se2, o);
        se3 += __shfl_xor_sync(0xFFFFFFFFu, se3, o);
    }
    float seh = myh < 2 ? (myh == 0 ? se0 : se1) : (myh == 2 ? se2 : se3);
    float r = 1.0f / (seh + EPSV);
    ax *= r; ay *= r; az *= r; aw *= r;

    if (LAYER == 1) {
        int d = lane * 4;
        float4 v;
        v.x = ax + bias[d + 0];
        v.y = ay + bias[d + 1];
        v.z = az + bias[d + 2];
        v.w = aw + bias[d + 3];
        v.x = v.x > 0.f ? v.x : (__expf(v.x) - 1.0f);
        v.y = v.y > 0.f ? v.y : (__expf(v.y) - 1.0f);
        v.z = v.z > 0.f ? v.z : (__expf(v.z) - 1.0f);
        v.w = v.w > 0.f ? v.w : (__expf(v.w) - 1.0f);
        *(float4*)(g_z + (size_t)n * DHID + d) = v;
    } else {
        int d = lane * 4;
        ax += bias[d + 0]; ay += bias[d + 1]; az += bias[d + 2]; aw += bias[d + 3];
#pragma unroll
        for (int o = 8; o <= 16; o <<= 1) {
            ax += __shfl_xor_sync(0xFFFFFFFFu, ax, o);
            ay += __shfl_xor_sync(0xFFFFFFFFu, ay, o);
            az += __shfl_xor_sync(0xFFFFFFFFu, az, o);
            aw += __shfl_xor_sync(0xFFFFFFFFu, aw, o);
        }
        if (lane < 8) {
            float4 v = make_float4(0.25f * ax, 0.25f * ay, 0.25f * az, 0.25f * aw);
            *(float4*)(g_z2 + (size_t)n * DHEAD + lane * 4) = v;
        }
    }
}

// ================= launch =================
extern "C" void kernel_launch(void* const* d_in, const int* in_sizes, int n_in,
                              void* d_out, int out_size) {
    const float* h   = (const float*)d_in[0];
    const int*   src = (const int*)d_in[1];
    const int*   dst = (const int*)d_in[2];
    const float* W1  = (const float*)d_in[3];
    const float* al1 = (const float*)d_in[4];
    const float* ar1 = (const float*)d_in[5];
    const float* b1  = (const float*)d_in[6];
    const float* W2  = (const float*)d_in[7];
    const float* al2 = (const float*)d_in[8];
    const float* ar2 = (const float*)d_in[9];
    const float* b2  = (const float*)d_in[10];
    const float* Wp  = (const float*)d_in[11];
    const float* bp  = (const float*)d_in[12];
    float* out = (float*)d_out;

    float *p_z, *p_z2;
    int *p_cnt;
    cudaGetSymbolAddress((void**)&p_z,   g_z);
    cudaGetSymbolAddress((void**)&p_z2,  g_z2);
    cudaGetSymbolAddress((void**)&p_cnt, g_cnt);

    const int TPB = 256;
    int gEdge4 = (NE / 4 + TPB - 1) / TPB;
    int gAgg   = (NN + 7) / 8;

    dim3 gemmGrid1(1, (NN + 63) / 64);              // N=128
    dim3 gemmGridP(OUTD / 128, (NN + 63) / 64);     // N=512

    // ---- fork: CSR build on side stream, GEMM1 on main stream ----
    cudaEventRecord(g_evFork, 0);
    cudaStreamWaitEvent(g_s2, g_evFork, 0);
    cudaMemsetAsync(p_cnt, 0, NN * sizeof(int), g_s2);
    k_count<<<gEdge4, TPB, 0, g_s2>>>((const int4*)dst);
    k_scan<<<1, 1024, 0, g_s2>>>();
    k_fill<<<gEdge4, TPB, 0, g_s2>>>((const int4*)src, (const int4*)dst);
    cudaEventRecord(g_evCsr, g_s2);

    // ===== layer 1 =====
    gemm_tc<1><<<gemmGrid1, 256, SMEM_BYTES>>>(h, W1, nullptr, nullptr, NN, DHID, DHID, al1, ar1);
    cudaStreamWaitEvent(0, g_evCsr, 0);   // join: agg needs CSR
    k_gat_agg<1><<<gAgg, 256>>>(b1);

    // ===== layer 2 =====
    gemm_tc<1><<<gemmGrid1, 256, SMEM_BYTES>>>(p_z, W2, nullptr, nullptr, NN, DHID, DHID, al2, ar2);
    k_gat_agg<2><<<gAgg, 256>>>(b2);

    // ===== projection head =====
    gemm_tc<0><<<gemmGridP, 256, SMEM_BYTES>>>(p_z2, Wp, bp, out, NN, OUTD, DHEAD, nullptr, nullptr);
}